// round 13
// baseline (speedup 1.0000x reference)
#include <cuda_runtime.h>
#include <math.h>
#include <stdint.h>

// Problem constants
#define NU 50000
#define NI 50000
#define NN 100000          // NU + NI
#define DD 64
#define NNZ 3200000
#define NLAYERS 3
#define NB 4096
#define L2_REG 1e-5f

#define SCAN_CHUNK 1024
#define SCAN_NBLK ((NN + SCAN_CHUNK - 1) / SCAN_CHUNK)   // 98
#define STAT_READY (1 << 30)
#define LOSS_NBLK (NB / 8)                               // 512 blocks of 8 warps

// ---------------- device scratch (no allocs allowed) ----------------
__device__ __align__(256) float g_E0[NN * DD];
__device__ __align__(256) float g_E1[NN * DD];
__device__ __align__(256) unsigned int g_B0[NN * 32];   // bf16x2 shadow of E0
__device__ __align__(256) unsigned int g_B1[NN * 32];   // bf16x2 shadow of E1
__device__ __align__(256) float g_alle[NN * DD * (NLAYERS + 1)];   // [N, 256]
__device__ int   g_deg[NN];
__device__ int   g_rowptr[NN + 1];
__device__ int   g_cursor[NN];
__device__ __align__(16) int2 g_edge[NNZ];
__device__ int   g_stat[SCAN_NBLK];
__device__ int   g_bar;
__device__ int   g_bar2;
__device__ int   g_done;
__device__ float g_acc[4];

// ---------------- helpers ----------------
typedef unsigned long long ull;

__device__ __forceinline__ ull fma2(ull a, ull b, ull c) {
    ull d;
    asm("fma.rn.f32x2 %0, %1, %2, %3;" : "=l"(d) : "l"(a), "l"(b), "l"(c));
    return d;
}
__device__ __forceinline__ ull pk2(float lo, float hi) {
    ull d;
    asm("mov.b64 %0, {%1, %2};" : "=l"(d) : "f"(lo), "f"(hi));
    return d;
}
__device__ __forceinline__ float2 upk(ull v) {
    float2 f;
    asm("mov.b64 {%0, %1}, %2;" : "=f"(f.x), "=f"(f.y) : "l"(v));
    return f;
}
__device__ __forceinline__ unsigned int bf2pack(float lo, float hi) {
    unsigned int r;
    asm("cvt.rn.bf16x2.f32 %0, %1, %2;" : "=r"(r) : "f"(hi), "f"(lo));
    return r;
}
__device__ __forceinline__ void bfma(ull& acc, unsigned int bits, ull vv) {
    unsigned int lo = bits << 16;
    unsigned int hi = bits & 0xffff0000u;
    ull pair;
    asm("mov.b64 %0, {%1, %2};" : "=l"(pair) : "r"(lo), "r"(hi));
    acc = fma2(pair, vv, acc);
}
__device__ __forceinline__ uint32_t tf32r(float x) {
    uint32_t r;
    asm("cvt.rna.tf32.f32 %0, %1;" : "=r"(r) : "f"(x));
    return r;
}

// m16n8k8 tf32 warp MMA (baseline PTX, sm_80+)
#define MMA_TF32(c, a, b) \
    asm volatile("mma.sync.aligned.m16n8k8.row.col.f32.tf32.tf32.f32 " \
        "{%0,%1,%2,%3}, {%4,%5,%6,%7}, {%8,%9}, {%0,%1,%2,%3};" \
        : "+f"((c)[0]), "+f"((c)[1]), "+f"((c)[2]), "+f"((c)[3]) \
        : "r"((a)[0]), "r"((a)[1]), "r"((a)[2]), "r"((a)[3]), \
          "r"((b)[0]), "r"((b)[1]))

// ---------------- 1: count + E init (fp32 + bf16 shadow) ----------------
__global__ void k_count_init(const int* __restrict__ rows,
                             const float* __restrict__ ue,
                             const float* __restrict__ ie) {
    int i = blockIdx.x * blockDim.x + threadIdx.x;
    if (i < NNZ) atomicAdd(&g_deg[rows[i]], 1);
    if (i < NN * (DD / 4)) {
        int n = i >> 4;
        int c = i & 15;
        const float4* src;
        int srow;
        if (n < NU) { src = (const float4*)ue; srow = n; }
        else        { src = (const float4*)ie; srow = n - NU; }
        float4 v = src[srow * 16 + c];
        ((float4*)g_E0)[i] = v;
        ((float4*)g_alle)[n * 64 + c] = v;
        uint2 b;
        b.x = bf2pack(v.x, v.y);
        b.y = bf2pack(v.z, v.w);
        ((uint2*)g_B0)[i] = b;
    }
    if (i < 4) g_acc[i] = 0.0f;
}

// ---------------- 2: fused scan + scatter ----------------
__global__ void k_scan_scatter(const int* __restrict__ rows,
                               const int* __restrict__ cols,
                               const float* __restrict__ vals) {
    __shared__ int s[SCAN_CHUNK];
    __shared__ int wsum[4];
    __shared__ int s_off;
    int b = blockIdx.x;
    int t = threadIdx.x;
    int i = b * SCAN_CHUNK + t;
    int v = (i < NN) ? g_deg[i] : 0;
    if (i < NN) g_deg[i] = 0;
    s[t] = v;
    __syncthreads();
    for (int off = 1; off < SCAN_CHUNK; off <<= 1) {
        int x = 0;
        if (t >= off) x = s[t - off];
        __syncthreads();
        s[t] += x;
        __syncthreads();
    }
    if (t == SCAN_CHUNK - 1) atomicExch(&g_stat[b], s[t] | STAT_READY);
    int part = 0;
    if (t < b) {
        int st;
        do { st = atomicAdd(&g_stat[t], 0); } while (!(st & STAT_READY));
        part = st & (STAT_READY - 1);
    }
    #pragma unroll
    for (int off = 16; off > 0; off >>= 1)
        part += __shfl_xor_sync(0xffffffffu, part, off);
    if ((t & 31) == 0 && (t >> 5) < 4) wsum[t >> 5] = part;
    __syncthreads();
    if (t == 0) s_off = wsum[0] + wsum[1] + wsum[2] + wsum[3];
    __syncthreads();
    int off = s_off;
    if (i < NN) {
        int incl = s[t] + off;
        g_rowptr[1 + i] = incl;
        g_cursor[i] = incl - v;
    }
    if (b == 0 && t == 0) g_rowptr[0] = 0;

    __threadfence();
    __syncthreads();
    if (t == 0) {
        atomicAdd(&g_bar, 1);
        while (atomicAdd(&g_bar, 0) < SCAN_NBLK) { }
        g_stat[b] = 0;
        int r2 = atomicAdd(&g_bar2, 1);
        if (r2 == SCAN_NBLK - 1) { g_bar = 0; g_bar2 = 0; }
    }
    __syncthreads();

    for (int e = b * SCAN_CHUNK + t; e < NNZ; e += SCAN_NBLK * SCAN_CHUNK) {
        int r = rows[e];
        int p = atomicAdd(&g_cursor[r], 1);
        int2 pr;
        pr.x = cols[e];
        pr.y = __float_as_int(vals[e]);
        g_edge[p] = pr;
    }
}

// ---------------- 3: FUSED layer: SpMM gather + tf32 MMA + epilogue -----------
// 256 threads, 128 nodes/block. Warp w gathers nodes w*16..w*16+15 directly
// into the tf32 staging tiles (A = Lmul+E, R = Lmul*E), then 8-warp MMA.
#define GP 68
#define OFF_AS 0
#define OFF_RS (128 * GP)
#define OFF_W1S (2 * 128 * GP)
#define OFF_W2S (2 * 128 * GP + 64 * GP)
#define OFF_BIAS (2 * 128 * GP + 2 * 64 * GP)
#define GEMM_SMEM_FLOATS (OFF_BIAS + 64)

__global__ void __launch_bounds__(256, 2) k_layer(int cur, int l,
                                                  const float* __restrict__ W1,
                                                  const float* __restrict__ b1,
                                                  const float* __restrict__ W2,
                                                  const float* __restrict__ b2) {
    extern __shared__ float sm[];
    __shared__ int2 sedge[8][32];
    uint32_t* Au  = (uint32_t*)(sm + OFF_AS);    // [128][GP] tf32 bits
    uint32_t* Ru  = (uint32_t*)(sm + OFF_RS);    // [128][GP]
    uint32_t* W1u = (uint32_t*)(sm + OFF_W1S);   // [64][GP]  W'[n][k]
    uint32_t* W2u = (uint32_t*)(sm + OFF_W2S);   // [64][GP]
    float* biasS  = sm + OFF_BIAS;

    const float*  Ecur  = cur ? g_E1 : g_E0;
    const uint4*  B4    = (const uint4*)(cur ? g_B1 : g_B0);
    float*        Enext = cur ? g_E0 : g_E1;
    unsigned int* Bnext = cur ? g_B0 : g_B1;

    int tid  = threadIdx.x;
    int wid  = tid >> 5;
    int lane = tid & 31;
    int g    = lane >> 2;        // MMA: 0..7
    int tg   = lane & 3;         // MMA: 0..3
    int eg   = lane >> 3;        // gather: edge group 0..3
    int sub  = lane & 7;         // gather: dim-octet 0..7
    int rw   = wid * 16;
    int n0 = blockIdx.x * 128;
    int lw = l * 64 * 64;
    int lb = l * 64;

    if (tid < 64) biasS[tid] = b1[lb + tid] + b2[lb + tid];

    // ---- stage W' (transposed), tf32 ----
    {
        int j  = tid >> 2;
        int kq = (tid & 3) * 16;
        #pragma unroll
        for (int kk = 0; kk < 16; kk++) {
            int k = kq + kk;
            W1u[j * GP + k] = tf32r(W1[lw + k * 64 + j]);
            W2u[j * GP + k] = tf32r(W2[lw + k * 64 + j]);
        }
    }

    // ---- gather phase: warp w handles 16 nodes, staging A/R directly ----
    const float4* EC4 = (const float4*)Ecur;
    for (int i = 0; i < 16; i++) {
        int node = n0 + rw + i;
        ull a0 = 0, a1 = 0, a2 = 0, a3 = 0;   // dims sub*8+{0,1},{2,3},{4,5},{6,7}
        int start = 0, end = 0;
        if (node < NN) {
            start = g_rowptr[node];
            end   = g_rowptr[node + 1];
        }
        int e0 = start;
        for (; e0 + 32 <= end; e0 += 32) {
            sedge[wid][lane] = g_edge[e0 + lane];
            __syncwarp();
            #pragma unroll
            for (int i0 = 0; i0 < 8; i0 += 4) {
                int2 eA = sedge[wid][4 * (i0 + 0) + eg];
                int2 eB = sedge[wid][4 * (i0 + 1) + eg];
                int2 eC = sedge[wid][4 * (i0 + 2) + eg];
                int2 eD = sedge[wid][4 * (i0 + 3) + eg];
                uint4 qA = B4[eA.x * 8 + sub];
                uint4 qB = B4[eB.x * 8 + sub];
                uint4 qC = B4[eC.x * 8 + sub];
                uint4 qD = B4[eD.x * 8 + sub];
                ull vA = pk2(__int_as_float(eA.y), __int_as_float(eA.y));
                ull vB = pk2(__int_as_float(eB.y), __int_as_float(eB.y));
                ull vC = pk2(__int_as_float(eC.y), __int_as_float(eC.y));
                ull vD = pk2(__int_as_float(eD.y), __int_as_float(eD.y));
                bfma(a0, qA.x, vA); bfma(a1, qA.y, vA); bfma(a2, qA.z, vA); bfma(a3, qA.w, vA);
                bfma(a0, qB.x, vB); bfma(a1, qB.y, vB); bfma(a2, qB.z, vB); bfma(a3, qB.w, vB);
                bfma(a0, qC.x, vC); bfma(a1, qC.y, vC); bfma(a2, qC.z, vC); bfma(a3, qC.w, vC);
                bfma(a0, qD.x, vD); bfma(a1, qD.y, vD); bfma(a2, qD.z, vD); bfma(a3, qD.w, vD);
            }
            __syncwarp();
        }
        int rem = end - e0;
        if (rem > 0) {
            sedge[wid][lane] = (lane < rem) ? g_edge[e0 + lane] : make_int2(0, 0);
            __syncwarp();
            int ngrp = (rem + 3) >> 2;
            for (int q = 0; q < ngrp; q++) {
                int2 ed = sedge[wid][4 * q + eg];
                uint4 qv = B4[ed.x * 8 + sub];
                ull vv = pk2(__int_as_float(ed.y), __int_as_float(ed.y));
                bfma(a0, qv.x, vv); bfma(a1, qv.y, vv); bfma(a2, qv.z, vv); bfma(a3, qv.w, vv);
            }
            __syncwarp();
        }
        // reduce across 4 edge groups (lane bits 3,4)
        float2 f0 = upk(a0), f1 = upk(a1), f2 = upk(a2), f3 = upk(a3);
        #pragma unroll
        for (int off = 8; off <= 16; off <<= 1) {
            f0.x += __shfl_xor_sync(0xffffffffu, f0.x, off);
            f0.y += __shfl_xor_sync(0xffffffffu, f0.y, off);
            f1.x += __shfl_xor_sync(0xffffffffu, f1.x, off);
            f1.y += __shfl_xor_sync(0xffffffffu, f1.y, off);
            f2.x += __shfl_xor_sync(0xffffffffu, f2.x, off);
            f2.y += __shfl_xor_sync(0xffffffffu, f2.y, off);
            f3.x += __shfl_xor_sync(0xffffffffu, f3.x, off);
            f3.y += __shfl_xor_sync(0xffffffffu, f3.y, off);
        }
        // lanes 0..7: add/mul fp32 E row, convert tf32, store to staging tiles
        if (lane < 8) {
            float4 e0v = make_float4(0, 0, 0, 0), e1v = make_float4(0, 0, 0, 0);
            if (node < NN) {
                e0v = EC4[node * 16 + sub * 2];
                e1v = EC4[node * 16 + sub * 2 + 1];
            }
            int row = rw + i;
            uint4 av0, av1, rv0, rv1;
            av0.x = tf32r(f0.x + e0v.x); av0.y = tf32r(f0.y + e0v.y);
            av0.z = tf32r(f1.x + e0v.z); av0.w = tf32r(f1.y + e0v.w);
            av1.x = tf32r(f2.x + e1v.x); av1.y = tf32r(f2.y + e1v.y);
            av1.z = tf32r(f3.x + e1v.z); av1.w = tf32r(f3.y + e1v.w);
            rv0.x = tf32r(f0.x * e0v.x); rv0.y = tf32r(f0.y * e0v.y);
            rv0.z = tf32r(f1.x * e0v.z); rv0.w = tf32r(f1.y * e0v.w);
            rv1.x = tf32r(f2.x * e1v.x); rv1.y = tf32r(f2.y * e1v.y);
            rv1.z = tf32r(f3.x * e1v.z); rv1.w = tf32r(f3.y * e1v.w);
            *(uint4*)&Au[row * GP + sub * 8]     = av0;
            *(uint4*)&Au[row * GP + sub * 8 + 4] = av1;
            *(uint4*)&Ru[row * GP + sub * 8]     = rv0;
            *(uint4*)&Ru[row * GP + sub * 8 + 4] = rv1;
        }
    }
    __syncthreads();

    // ---- MMA: warp w -> m16 tile rows rw..rw+15, all 64 cols ----
    float c[8][4];
    #pragma unroll
    for (int jt = 0; jt < 8; jt++) {
        float bv0 = biasS[8 * jt + 2 * tg];
        float bv1 = biasS[8 * jt + 2 * tg + 1];
        c[jt][0] = bv0; c[jt][1] = bv1;
        c[jt][2] = bv0; c[jt][3] = bv1;
    }
    #pragma unroll 2
    for (int kb = 0; kb < 64; kb += 8) {
        uint32_t af[4], rf[4];
        int rr = rw + g;
        af[0] = Au[rr * GP + kb + tg];
        af[1] = Au[(rr + 8) * GP + kb + tg];
        af[2] = Au[rr * GP + kb + tg + 4];
        af[3] = Au[(rr + 8) * GP + kb + tg + 4];
        rf[0] = Ru[rr * GP + kb + tg];
        rf[1] = Ru[(rr + 8) * GP + kb + tg];
        rf[2] = Ru[rr * GP + kb + tg + 4];
        rf[3] = Ru[(rr + 8) * GP + kb + tg + 4];
        #pragma unroll
        for (int jt = 0; jt < 8; jt++) {
            uint32_t w1f[2], w2f[2];
            int nn = 8 * jt + g;
            w1f[0] = W1u[nn * GP + kb + tg];
            w1f[1] = W1u[nn * GP + kb + tg + 4];
            w2f[0] = W2u[nn * GP + kb + tg];
            w2f[1] = W2u[nn * GP + kb + tg + 4];
            MMA_TF32(c[jt], af, w1f);
            MMA_TF32(c[jt], rf, w2f);
        }
    }

    // ---- leaky relu + row sq ----
    float sq[2] = {0, 0};
    #pragma unroll
    for (int jt = 0; jt < 8; jt++) {
        #pragma unroll
        for (int q = 0; q < 4; q++) {
            float v = c[jt][q];
            v = (v >= 0.0f) ? v : 0.2f * v;
            c[jt][q] = v;
            sq[q >> 1] = fmaf(v, v, sq[q >> 1]);
        }
    }
    sq[0] += __shfl_xor_sync(0xffffffffu, sq[0], 1);
    sq[0] += __shfl_xor_sync(0xffffffffu, sq[0], 2);
    sq[1] += __shfl_xor_sync(0xffffffffu, sq[1], 1);
    sq[1] += __shfl_xor_sync(0xffffffffu, sq[1], 2);

    __syncthreads();   // fragment LDS done -> reuse As/Rs
    float* OutS = sm + OFF_AS;        // [128][GP]
    float* sqS  = sm + OFF_RS;        // [128]
    {
        int rA = rw + g;
        #pragma unroll
        for (int jt = 0; jt < 8; jt++) {
            *(float2*)&OutS[rA * GP + 8 * jt + 2 * tg] =
                make_float2(c[jt][0], c[jt][1]);
            *(float2*)&OutS[(rA + 8) * GP + 8 * jt + 2 * tg] =
                make_float2(c[jt][2], c[jt][3]);
        }
        if (tg == 0) {
            sqS[rA]     = sq[0];
            sqS[rA + 8] = sq[1];
        }
    }
    __syncthreads();

    // ---- coalesced global writes (layer 2 skips E/B: only alle is consumed) --
    {
        int tx = tid & 15;
        int ty = tid >> 4;
        int colblk = (l + 1) * 64;
        #pragma unroll 4
        for (int rr2 = 0; rr2 < 8; rr2++) {
            int r = ty * 8 + rr2;
            int n = n0 + r;
            if (n < NN) {
                float inv = 1.0f / fmaxf(sqrtf(sqS[r]), 1e-12f);
                const float* o = &OutS[r * GP + tx * 4];
                float4 v = make_float4(o[0], o[1], o[2], o[3]);
                if (l < NLAYERS - 1) {
                    *(float4*)&Enext[n * DD + tx * 4] = v;
                    uint2 bv;
                    bv.x = bf2pack(v.x, v.y);
                    bv.y = bf2pack(v.z, v.w);
                    *(uint2*)&Bnext[n * 32 + tx * 2] = bv;
                }
                *(float4*)&g_alle[n * 256 + colblk + tx * 4] =
                    make_float4(v.x * inv, v.y * inv, v.z * inv, v.w * inv);
            }
        }
    }
}

// ---------------- 4: loss + fused finalize ----------------
__global__ void k_loss(const int* __restrict__ users,
                       const int* __restrict__ pos,
                       const int* __restrict__ neg,
                       float* __restrict__ out) {
    int warp = (blockIdx.x * blockDim.x + threadIdx.x) >> 5;
    int lane = threadIdx.x & 31;
    if (warp < NB) {
        int uu = users[warp];
        int pp = pos[warp];
        int nn = neg[warp];
        const float4* A4 = (const float4*)g_alle;
        float pd = 0, nd = 0, su = 0, sp = 0, sn = 0;
        #pragma unroll
        for (int t = 0; t < 2; t++) {
            float4 u = A4[uu * 64 + lane * 2 + t];
            float4 p = A4[pp * 64 + lane * 2 + t];
            float4 q = A4[nn * 64 + lane * 2 + t];
            pd += u.x * p.x + u.y * p.y + u.z * p.z + u.w * p.w;
            nd += u.x * q.x + u.y * q.y + u.z * q.z + u.w * q.w;
            su += u.x * u.x + u.y * u.y + u.z * u.z + u.w * u.w;
            sp += p.x * p.x + p.y * p.y + p.z * p.z + p.w * p.w;
            sn += q.x * q.x + q.y * q.y + q.z * q.z + q.w * q.w;
        }
        #pragma unroll
        for (int off = 16; off > 0; off >>= 1) {
            pd += __shfl_xor_sync(0xffffffffu, pd, off);
            nd += __shfl_xor_sync(0xffffffffu, nd, off);
            su += __shfl_xor_sync(0xffffffffu, su, off);
            sp += __shfl_xor_sync(0xffffffffu, sp, off);
            sn += __shfl_xor_sync(0xffffffffu, sn, off);
        }
        if (lane == 0) {
            float d = pd - nd;
            float ls = fminf(d, 0.0f) - log1pf(expf(-fabsf(d)));
            atomicAdd(&g_acc[0], ls);
            atomicAdd(&g_acc[1], su);
            atomicAdd(&g_acc[2], sp);
            atomicAdd(&g_acc[3], sn);
        }
    }
    __threadfence();
    __syncthreads();
    if (threadIdx.x == 0) {
        int r = atomicAdd(&g_done, 1);
        if (r == LOSS_NBLK - 1) {
            float a0 = atomicAdd(&g_acc[0], 0.0f);
            float a1 = atomicAdd(&g_acc[1], 0.0f);
            float a2 = atomicAdd(&g_acc[2], 0.0f);
            float a3 = atomicAdd(&g_acc[3], 0.0f);
            float bpr = -a0 / (float)NB;
            float l2norm = (a1 + a2 + sqrtf(a3)) * 0.5f;
            out[0] = bpr + L2_REG * l2norm / (float)NB;
            g_acc[0] = 0.0f; g_acc[1] = 0.0f; g_acc[2] = 0.0f; g_acc[3] = 0.0f;
            g_done = 0;
        }
    }
}

// ---------------- launch ----------------
extern "C" void kernel_launch(void* const* d_in, const int* in_sizes, int n_in,
                              void* d_out, int out_size) {
    const int*   users = (const int*)d_in[0];
    const int*   pos   = (const int*)d_in[1];
    const int*   neg   = (const int*)d_in[2];
    const int*   rows  = (const int*)d_in[3];
    const int*   cols  = (const int*)d_in[4];
    const float* vals  = (const float*)d_in[5];
    const float* ue    = (const float*)d_in[6];
    const float* ie    = (const float*)d_in[7];
    const float* W1    = (const float*)d_in[8];
    const float* b1    = (const float*)d_in[9];
    const float* W2    = (const float*)d_in[10];
    const float* b2    = (const float*)d_in[11];
    float* out = (float*)d_out;

    cudaFuncSetAttribute(k_layer, cudaFuncAttributeMaxDynamicSharedMemorySize,
                         GEMM_SMEM_FLOATS * sizeof(float));

    k_count_init<<<(NNZ + 255) / 256, 256>>>(rows, ue, ie);
    k_scan_scatter<<<SCAN_NBLK, SCAN_CHUNK>>>(rows, cols, vals);

    int cur = 0;
    for (int l = 0; l < NLAYERS; l++) {
        k_layer<<<(NN + 127) / 128, 256, GEMM_SMEM_FLOATS * sizeof(float)>>>(
            cur, l, W1, b1, W2, b2);
        cur ^= 1;
    }

    k_loss<<<LOSS_NBLK, 256>>>(users, pos, neg, out);
}

// round 14
// speedup vs baseline: 1.2030x; 1.2030x over previous
#include <cuda_runtime.h>
#include <math.h>
#include <stdint.h>

// Problem constants
#define NU 50000
#define NI 50000
#define NN 100000          // NU + NI
#define DD 64
#define NNZ 3200000
#define NLAYERS 3
#define NB 4096
#define L2_REG 1e-5f

#define SCAN_CHUNK 1024
#define SCAN_NBLK ((NN + SCAN_CHUNK - 1) / SCAN_CHUNK)   // 98
#define STAT_READY (1 << 30)
#define LOSS_NBLK (NB / 8)                               // 512 blocks of 8 warps

// ---------------- device scratch (no allocs allowed) ----------------
__device__ __align__(256) float g_E0[NN * DD];
__device__ __align__(256) float g_E1[NN * DD];
__device__ __align__(256) unsigned int g_B0[NN * 32];   // bf16x2 shadow of E0
__device__ __align__(256) unsigned int g_B1[NN * 32];   // bf16x2 shadow of E1
__device__ __align__(256) float g_Lmul[NN * DD];
__device__ __align__(256) float g_alle[NN * DD * (NLAYERS + 1)];   // [N, 256]
__device__ int   g_deg[NN];
__device__ int   g_rowptr[NN + 1];
__device__ int   g_cursor[NN];
__device__ __align__(16) int2 g_edge[NNZ];
__device__ int   g_stat[SCAN_NBLK];
__device__ int   g_bar;
__device__ int   g_bar2;
__device__ int   g_done;
__device__ float g_acc[4];

// ---------------- helpers ----------------
typedef unsigned long long ull;

__device__ __forceinline__ ull fma2(ull a, ull b, ull c) {
    ull d;
    asm("fma.rn.f32x2 %0, %1, %2, %3;" : "=l"(d) : "l"(a), "l"(b), "l"(c));
    return d;
}
__device__ __forceinline__ ull pk2(float lo, float hi) {
    ull d;
    asm("mov.b64 %0, {%1, %2};" : "=l"(d) : "f"(lo), "f"(hi));
    return d;
}
__device__ __forceinline__ float2 upk(ull v) {
    float2 f;
    asm("mov.b64 {%0, %1}, %2;" : "=f"(f.x), "=f"(f.y) : "l"(v));
    return f;
}
__device__ __forceinline__ unsigned int bf2pack(float lo, float hi) {
    unsigned int r;
    asm("cvt.rn.bf16x2.f32 %0, %1, %2;" : "=r"(r) : "f"(hi), "f"(lo));
    return r;
}
__device__ __forceinline__ void bfma(ull& acc, unsigned int bits, ull vv) {
    unsigned int lo = bits << 16;
    unsigned int hi = bits & 0xffff0000u;
    ull pair;
    asm("mov.b64 %0, {%1, %2};" : "=l"(pair) : "r"(lo), "r"(hi));
    acc = fma2(pair, vv, acc);
}
__device__ __forceinline__ uint32_t tf32r(float x) {
    uint32_t r;
    asm("cvt.rna.tf32.f32 %0, %1;" : "=r"(r) : "f"(x));
    return r;
}

// m16n8k8 tf32 warp MMA (baseline PTX, sm_80+)
#define MMA_TF32(c, a, b) \
    asm volatile("mma.sync.aligned.m16n8k8.row.col.f32.tf32.tf32.f32 " \
        "{%0,%1,%2,%3}, {%4,%5,%6,%7}, {%8,%9}, {%0,%1,%2,%3};" \
        : "+f"((c)[0]), "+f"((c)[1]), "+f"((c)[2]), "+f"((c)[3]) \
        : "r"((a)[0]), "r"((a)[1]), "r"((a)[2]), "r"((a)[3]), \
          "r"((b)[0]), "r"((b)[1]))

// ---------------- 1: count + E init (fp32 + bf16 shadow) ----------------
__global__ void k_count_init(const int* __restrict__ rows,
                             const float* __restrict__ ue,
                             const float* __restrict__ ie) {
    int i = blockIdx.x * blockDim.x + threadIdx.x;
    if (i < NNZ) atomicAdd(&g_deg[rows[i]], 1);
    if (i < NN * (DD / 4)) {
        int n = i >> 4;
        int c = i & 15;
        const float4* src;
        int srow;
        if (n < NU) { src = (const float4*)ue; srow = n; }
        else        { src = (const float4*)ie; srow = n - NU; }
        float4 v = src[srow * 16 + c];
        ((float4*)g_E0)[i] = v;
        ((float4*)g_alle)[n * 64 + c] = v;
        uint2 b;
        b.x = bf2pack(v.x, v.y);
        b.y = bf2pack(v.z, v.w);
        ((uint2*)g_B0)[i] = b;
    }
}

// ---------------- 2: fused scan + scatter ----------------
__global__ void k_scan_scatter(const int* __restrict__ rows,
                               const int* __restrict__ cols,
                               const float* __restrict__ vals) {
    __shared__ int s[SCAN_CHUNK];
    __shared__ int wsum[4];
    __shared__ int s_off;
    int b = blockIdx.x;
    int t = threadIdx.x;
    int i = b * SCAN_CHUNK + t;
    int v = (i < NN) ? g_deg[i] : 0;
    if (i < NN) g_deg[i] = 0;
    s[t] = v;
    __syncthreads();
    for (int off = 1; off < SCAN_CHUNK; off <<= 1) {
        int x = 0;
        if (t >= off) x = s[t - off];
        __syncthreads();
        s[t] += x;
        __syncthreads();
    }
    if (t == SCAN_CHUNK - 1) atomicExch(&g_stat[b], s[t] | STAT_READY);
    int part = 0;
    if (t < b) {
        int st;
        do { st = atomicAdd(&g_stat[t], 0); } while (!(st & STAT_READY));
        part = st & (STAT_READY - 1);
    }
    #pragma unroll
    for (int off = 16; off > 0; off >>= 1)
        part += __shfl_xor_sync(0xffffffffu, part, off);
    if ((t & 31) == 0 && (t >> 5) < 4) wsum[t >> 5] = part;
    __syncthreads();
    if (t == 0) s_off = wsum[0] + wsum[1] + wsum[2] + wsum[3];
    __syncthreads();
    int off = s_off;
    if (i < NN) {
        int incl = s[t] + off;
        g_rowptr[1 + i] = incl;
        g_cursor[i] = incl - v;
    }
    if (b == 0 && t == 0) g_rowptr[0] = 0;

    __threadfence();
    __syncthreads();
    if (t == 0) {
        atomicAdd(&g_bar, 1);
        while (atomicAdd(&g_bar, 0) < SCAN_NBLK) { }
        g_stat[b] = 0;
        int r2 = atomicAdd(&g_bar2, 1);
        if (r2 == SCAN_NBLK - 1) { g_bar = 0; g_bar2 = 0; }
    }
    __syncthreads();

    for (int e = b * SCAN_CHUNK + t; e < NNZ; e += SCAN_NBLK * SCAN_CHUNK) {
        int r = rows[e];
        int p = atomicAdd(&g_cursor[r], 1);
        int2 pr;
        pr.x = cols[e];
        pr.y = __float_as_int(vals[e]);
        g_edge[p] = pr;
    }
}

// ---------------- 3: SpMM — warp/node, bf16 rows, 4 edges per LDG.128 ----------
__global__ void __launch_bounds__(256) k_spmm(int cur) {
    const uint4* __restrict__ B4 = (const uint4*)(cur ? g_B1 : g_B0);
    __shared__ int2 sedge[8][32];
    int warp = (blockIdx.x * blockDim.x + threadIdx.x) >> 5;
    int wid  = threadIdx.x >> 5;
    int lane = threadIdx.x & 31;
    int g    = lane >> 3;
    int sub  = lane & 7;
    if (warp >= NN) return;
    int start = g_rowptr[warp];
    int end   = g_rowptr[warp + 1];
    ull a0 = 0, a1 = 0, a2 = 0, a3 = 0;
    int e0 = start;
    for (; e0 + 32 <= end; e0 += 32) {
        sedge[wid][lane] = g_edge[e0 + lane];
        __syncwarp();
        #pragma unroll
        for (int i0 = 0; i0 < 8; i0 += 4) {
            int2 eA = sedge[wid][4 * (i0 + 0) + g];
            int2 eB = sedge[wid][4 * (i0 + 1) + g];
            int2 eC = sedge[wid][4 * (i0 + 2) + g];
            int2 eD = sedge[wid][4 * (i0 + 3) + g];
            uint4 qA = B4[eA.x * 8 + sub];
            uint4 qB = B4[eB.x * 8 + sub];
            uint4 qC = B4[eC.x * 8 + sub];
            uint4 qD = B4[eD.x * 8 + sub];
            ull vA = pk2(__int_as_float(eA.y), __int_as_float(eA.y));
            ull vB = pk2(__int_as_float(eB.y), __int_as_float(eB.y));
            ull vC = pk2(__int_as_float(eC.y), __int_as_float(eC.y));
            ull vD = pk2(__int_as_float(eD.y), __int_as_float(eD.y));
            bfma(a0, qA.x, vA); bfma(a1, qA.y, vA); bfma(a2, qA.z, vA); bfma(a3, qA.w, vA);
            bfma(a0, qB.x, vB); bfma(a1, qB.y, vB); bfma(a2, qB.z, vB); bfma(a3, qB.w, vB);
            bfma(a0, qC.x, vC); bfma(a1, qC.y, vC); bfma(a2, qC.z, vC); bfma(a3, qC.w, vC);
            bfma(a0, qD.x, vD); bfma(a1, qD.y, vD); bfma(a2, qD.z, vD); bfma(a3, qD.w, vD);
        }
        __syncwarp();
    }
    int rem = end - e0;
    if (rem > 0) {
        sedge[wid][lane] = (lane < rem) ? g_edge[e0 + lane] : make_int2(0, 0);
        __syncwarp();
        int ngrp = (rem + 3) >> 2;
        for (int i = 0; i < ngrp; i++) {
            int2 ed = sedge[wid][4 * i + g];
            uint4 q = B4[ed.x * 8 + sub];
            ull vv = pk2(__int_as_float(ed.y), __int_as_float(ed.y));
            bfma(a0, q.x, vv); bfma(a1, q.y, vv); bfma(a2, q.z, vv); bfma(a3, q.w, vv);
        }
    }
    float2 f0 = upk(a0), f1 = upk(a1), f2 = upk(a2), f3 = upk(a3);
    #pragma unroll
    for (int off = 8; off <= 16; off <<= 1) {
        f0.x += __shfl_xor_sync(0xffffffffu, f0.x, off);
        f0.y += __shfl_xor_sync(0xffffffffu, f0.y, off);
        f1.x += __shfl_xor_sync(0xffffffffu, f1.x, off);
        f1.y += __shfl_xor_sync(0xffffffffu, f1.y, off);
        f2.x += __shfl_xor_sync(0xffffffffu, f2.x, off);
        f2.y += __shfl_xor_sync(0xffffffffu, f2.y, off);
        f3.x += __shfl_xor_sync(0xffffffffu, f3.x, off);
        f3.y += __shfl_xor_sync(0xffffffffu, f3.y, off);
    }
    if (lane < 8) {
        *(float4*)&g_Lmul[warp * DD + lane * 8]     = make_float4(f0.x, f0.y, f1.x, f1.y);
        *(float4*)&g_Lmul[warp * DD + lane * 8 + 4] = make_float4(f2.x, f2.y, f3.x, f3.y);
    }
}

// ---------------- 4: GEMM via mma.sync tf32 — 128 rows/block, 8 warps ---------
// Warp w: rows w*16..w*16+15 (one m16 tile), all 64 cols, A & R operands.
// W staging now COALESCED global reads (k=i>>6, n=i&63) -> transposed smem.
#define GP 68
#define OFF_AS 0
#define OFF_RS (128 * GP)
#define OFF_W1S (2 * 128 * GP)
#define OFF_W2S (2 * 128 * GP + 64 * GP)
#define OFF_BIAS (2 * 128 * GP + 2 * 64 * GP)
#define GEMM_SMEM_FLOATS (OFF_BIAS + 64)

__global__ void __launch_bounds__(256, 2) k_gemm(int cur, int l,
                                                 const float* __restrict__ W1,
                                                 const float* __restrict__ b1,
                                                 const float* __restrict__ W2,
                                                 const float* __restrict__ b2) {
    extern __shared__ float sm[];
    uint32_t* Au  = (uint32_t*)(sm + OFF_AS);    // [128][GP] tf32 bits
    uint32_t* Ru  = (uint32_t*)(sm + OFF_RS);    // [128][GP]
    uint32_t* W1u = (uint32_t*)(sm + OFF_W1S);   // [64][GP]  W'[n][k]
    uint32_t* W2u = (uint32_t*)(sm + OFF_W2S);   // [64][GP]
    float* biasS  = sm + OFF_BIAS;

    const float*  Ecur  = cur ? g_E1 : g_E0;
    float*        Enext = cur ? g_E0 : g_E1;
    unsigned int* Bnext = cur ? g_B0 : g_B1;

    int tid  = threadIdx.x;
    int wid  = tid >> 5;
    int lane = tid & 31;
    int g    = lane >> 2;        // 0..7
    int tg   = lane & 3;         // 0..3
    int rw   = wid * 16;         // warp's m16 tile base row
    int n0 = blockIdx.x * 128;
    int lw = l * 64 * 64;
    int lb = l * 64;

    if (tid < 64) biasS[tid] = b1[lb + tid] + b2[lb + tid];

    // ---- stage A = Lmul+E, R = Lmul*E (tf32-rounded); half-row per thread ----
    {
        int row  = tid >> 1;
        int half = (tid & 1) * 8;
        int n = n0 + row;
        const float4* LM4 = (const float4*)g_Lmul;
        const float4* EC4 = (const float4*)Ecur;
        #pragma unroll
        for (int cc = 0; cc < 8; cc++) {
            int c = half + cc;
            float4 lm = make_float4(0, 0, 0, 0), ev = make_float4(0, 0, 0, 0);
            if (n < NN) {
                lm = LM4[n * 16 + c];
                ev = EC4[n * 16 + c];
            }
            uint4 av, rv;
            av.x = tf32r(lm.x + ev.x); av.y = tf32r(lm.y + ev.y);
            av.z = tf32r(lm.z + ev.z); av.w = tf32r(lm.w + ev.w);
            rv.x = tf32r(lm.x * ev.x); rv.y = tf32r(lm.y * ev.y);
            rv.z = tf32r(lm.z * ev.z); rv.w = tf32r(lm.w * ev.w);
            *(uint4*)&Au[row * GP + c * 4] = av;
            *(uint4*)&Ru[row * GP + c * 4] = rv;
        }
    }
    // ---- stage W' (transposed) with COALESCED global reads ----
    // i = k*64 + n (row-major W). Read W[lw+i] linearly; write W'[n][k].
    for (int i = tid; i < 4096; i += 256) {
        int k = i >> 6;
        int n = i & 63;
        W1u[n * GP + k] = tf32r(W1[lw + i]);
        W2u[n * GP + k] = tf32r(W2[lw + i]);
    }
    __syncthreads();

    // ---- accumulators: c[jt] covers rows {rw+g, rw+8+g}, cols {8jt+2tg, +1}
    float c[8][4];
    #pragma unroll
    for (int jt = 0; jt < 8; jt++) {
        float bv0 = biasS[8 * jt + 2 * tg];
        float bv1 = biasS[8 * jt + 2 * tg + 1];
        c[jt][0] = bv0; c[jt][1] = bv1;
        c[jt][2] = bv0; c[jt][3] = bv1;
    }

    #pragma unroll 2
    for (int kb = 0; kb < 64; kb += 8) {
        uint32_t af[4], rf[4];
        int rr = rw + g;
        af[0] = Au[rr * GP + kb + tg];
        af[1] = Au[(rr + 8) * GP + kb + tg];
        af[2] = Au[rr * GP + kb + tg + 4];
        af[3] = Au[(rr + 8) * GP + kb + tg + 4];
        rf[0] = Ru[rr * GP + kb + tg];
        rf[1] = Ru[(rr + 8) * GP + kb + tg];
        rf[2] = Ru[rr * GP + kb + tg + 4];
        rf[3] = Ru[(rr + 8) * GP + kb + tg + 4];
        #pragma unroll
        for (int jt = 0; jt < 8; jt++) {
            uint32_t w1f[2], w2f[2];
            int nn = 8 * jt + g;
            w1f[0] = W1u[nn * GP + kb + tg];
            w1f[1] = W1u[nn * GP + kb + tg + 4];
            w2f[0] = W2u[nn * GP + kb + tg];
            w2f[1] = W2u[nn * GP + kb + tg + 4];
            MMA_TF32(c[jt], af, w1f);
            MMA_TF32(c[jt], rf, w2f);
        }
    }

    // ---- leaky relu + per-row sq partials ----
    float sq[2] = {0, 0};
    #pragma unroll
    for (int jt = 0; jt < 8; jt++) {
        #pragma unroll
        for (int q = 0; q < 4; q++) {
            float v = c[jt][q];
            v = (v >= 0.0f) ? v : 0.2f * v;
            c[jt][q] = v;
            sq[q >> 1] = fmaf(v, v, sq[q >> 1]);
        }
    }
    sq[0] += __shfl_xor_sync(0xffffffffu, sq[0], 1);
    sq[0] += __shfl_xor_sync(0xffffffffu, sq[0], 2);
    sq[1] += __shfl_xor_sync(0xffffffffu, sq[1], 1);
    sq[1] += __shfl_xor_sync(0xffffffffu, sq[1], 2);

    __syncthreads();   // all fragment LDS done -> safe to reuse As/Rs
    float* OutS = sm + OFF_AS;        // [128][GP]
    float* sqS  = sm + OFF_RS;        // [128]
    {
        int rA = rw + g;
        #pragma unroll
        for (int jt = 0; jt < 8; jt++) {
            *(float2*)&OutS[rA * GP + 8 * jt + 2 * tg] =
                make_float2(c[jt][0], c[jt][1]);
            *(float2*)&OutS[(rA + 8) * GP + 8 * jt + 2 * tg] =
                make_float2(c[jt][2], c[jt][3]);
        }
        if (tg == 0) {
            sqS[rA]     = sq[0];
            sqS[rA + 8] = sq[1];
        }
    }
    __syncthreads();

    // ---- coalesced global writes (last layer: only alle is consumed) ----
    {
        int tx = tid & 15;
        int ty = tid >> 4;           // 0..15
        int colblk = (l + 1) * 64;
        #pragma unroll 4
        for (int rr = 0; rr < 8; rr++) {
            int r = ty * 8 + rr;
            int n = n0 + r;
            if (n < NN) {
                float inv = 1.0f / fmaxf(sqrtf(sqS[r]), 1e-12f);
                const float* o = &OutS[r * GP + tx * 4];
                float4 v = make_float4(o[0], o[1], o[2], o[3]);
                if (l < NLAYERS - 1) {
                    *(float4*)&Enext[n * DD + tx * 4] = v;
                    uint2 bv;
                    bv.x = bf2pack(v.x, v.y);
                    bv.y = bf2pack(v.z, v.w);
                    *(uint2*)&Bnext[n * 32 + tx * 2] = bv;
                }
                *(float4*)&g_alle[n * 256 + colblk + tx * 4] =
                    make_float4(v.x * inv, v.y * inv, v.z * inv, v.w * inv);
            }
        }
    }
}

// ---------------- 5: loss + fused finalize ----------------
__global__ void k_loss(const int* __restrict__ users,
                       const int* __restrict__ pos,
                       const int* __restrict__ neg,
                       float* __restrict__ out) {
    int warp = (blockIdx.x * blockDim.x + threadIdx.x) >> 5;
    int lane = threadIdx.x & 31;
    if (warp < NB) {
        int uu = users[warp];
        int pp = pos[warp];
        int nn = neg[warp];
        const float4* A4 = (const float4*)g_alle;
        float pd = 0, nd = 0, su = 0, sp = 0, sn = 0;
        #pragma unroll
        for (int t = 0; t < 2; t++) {
            float4 u = A4[uu * 64 + lane * 2 + t];
            float4 p = A4[pp * 64 + lane * 2 + t];
            float4 q = A4[nn * 64 + lane * 2 + t];
            pd += u.x * p.x + u.y * p.y + u.z * p.z + u.w * p.w;
            nd += u.x * q.x + u.y * q.y + u.z * q.z + u.w * q.w;
            su += u.x * u.x + u.y * u.y + u.z * u.z + u.w * u.w;
            sp += p.x * p.x + p.y * p.y + p.z * p.z + p.w * p.w;
            sn += q.x * q.x + q.y * q.y + q.z * q.z + q.w * q.w;
        }
        #pragma unroll
        for (int off = 16; off > 0; off >>= 1) {
            pd += __shfl_xor_sync(0xffffffffu, pd, off);
            nd += __shfl_xor_sync(0xffffffffu, nd, off);
            su += __shfl_xor_sync(0xffffffffu, su, off);
            sp += __shfl_xor_sync(0xffffffffu, sp, off);
            sn += __shfl_xor_sync(0xffffffffu, sn, off);
        }
        if (lane == 0) {
            float d = pd - nd;
            float ls = fminf(d, 0.0f) - log1pf(expf(-fabsf(d)));
            atomicAdd(&g_acc[0], ls);
            atomicAdd(&g_acc[1], su);
            atomicAdd(&g_acc[2], sp);
            atomicAdd(&g_acc[3], sn);
        }
    }
    __threadfence();
    __syncthreads();
    if (threadIdx.x == 0) {
        int r = atomicAdd(&g_done, 1);
        if (r == LOSS_NBLK - 1) {
            float a0 = atomicAdd(&g_acc[0], 0.0f);
            float a1 = atomicAdd(&g_acc[1], 0.0f);
            float a2 = atomicAdd(&g_acc[2], 0.0f);
            float a3 = atomicAdd(&g_acc[3], 0.0f);
            float bpr = -a0 / (float)NB;
            float l2norm = (a1 + a2 + sqrtf(a3)) * 0.5f;
            out[0] = bpr + L2_REG * l2norm / (float)NB;
            g_acc[0] = 0.0f; g_acc[1] = 0.0f; g_acc[2] = 0.0f; g_acc[3] = 0.0f;
            g_done = 0;
        }
    }
}

// ---------------- launch ----------------
extern "C" void kernel_launch(void* const* d_in, const int* in_sizes, int n_in,
                              void* d_out, int out_size) {
    const int*   users = (const int*)d_in[0];
    const int*   pos   = (const int*)d_in[1];
    const int*   neg   = (const int*)d_in[2];
    const int*   rows  = (const int*)d_in[3];
    const int*   cols  = (const int*)d_in[4];
    const float* vals  = (const float*)d_in[5];
    const float* ue    = (const float*)d_in[6];
    const float* ie    = (const float*)d_in[7];
    const float* W1    = (const float*)d_in[8];
    const float* b1    = (const float*)d_in[9];
    const float* W2    = (const float*)d_in[10];
    const float* b2    = (const float*)d_in[11];
    float* out = (float*)d_out;

    cudaFuncSetAttribute(k_gemm, cudaFuncAttributeMaxDynamicSharedMemorySize,
                         GEMM_SMEM_FLOATS * sizeof(float));

    k_count_init<<<(NNZ + 255) / 256, 256>>>(rows, ue, ie);
    k_scan_scatter<<<SCAN_NBLK, SCAN_CHUNK>>>(rows, cols, vals);

    int cur = 0;
    for (int l = 0; l < NLAYERS; l++) {
        k_spmm<<<(NN + 7) / 8, 256>>>(cur);
        k_gemm<<<(NN + 127) / 128, 256, GEMM_SMEM_FLOATS * sizeof(float)>>>(
            cur, l, W1, b1, W2, b2);
        cur ^= 1;
    }

    k_loss<<<LOSS_NBLK, 256>>>(users, pos, neg, out);
}

// round 15
// speedup vs baseline: 1.2760x; 1.0606x over previous
#include <cuda_runtime.h>
#include <math.h>
#include <stdint.h>

// Problem constants
#define NU 50000
#define NI 50000
#define NN 100000          // NU + NI
#define DD 64
#define NNZ 3200000
#define NLAYERS 3
#define NB 4096
#define L2_REG 1e-5f

#define SCAN_CHUNK 1024
#define SCAN_NBLK ((NN + SCAN_CHUNK - 1) / SCAN_CHUNK)   // 98
#define STAT_READY (1 << 30)
#define LOSS_NBLK (NB / 8)                               // 512 blocks of 8 warps

// ---------------- device scratch (no allocs allowed) ----------------
__device__ __align__(256) float g_E0[NN * DD];
__device__ __align__(256) float g_E1[NN * DD];
__device__ __align__(256) unsigned int g_B0[NN * 32];   // bf16x2 shadow of E0
__device__ __align__(256) unsigned int g_B1[NN * 32];   // bf16x2 shadow of E1
__device__ __align__(256) float g_Lmul[NN * DD];
__device__ __align__(256) float g_alle[NN * DD * (NLAYERS + 1)];   // [N, 256]
__device__ int   g_deg[NN];
__device__ int   g_rowptr[NN + 1];
__device__ int   g_cursor[NN];
__device__ __align__(16) int2 g_edge[NNZ];
__device__ int   g_stat[SCAN_NBLK];
__device__ int   g_bar;
__device__ int   g_bar2;
__device__ int   g_done;
__device__ float g_acc[4];

// ---------------- helpers ----------------
typedef unsigned long long ull;

__device__ __forceinline__ ull fma2(ull a, ull b, ull c) {
    ull d;
    asm("fma.rn.f32x2 %0, %1, %2, %3;" : "=l"(d) : "l"(a), "l"(b), "l"(c));
    return d;
}
__device__ __forceinline__ ull pk2(float lo, float hi) {
    ull d;
    asm("mov.b64 %0, {%1, %2};" : "=l"(d) : "f"(lo), "f"(hi));
    return d;
}
__device__ __forceinline__ float2 upk(ull v) {
    float2 f;
    asm("mov.b64 {%0, %1}, %2;" : "=f"(f.x), "=f"(f.y) : "l"(v));
    return f;
}
__device__ __forceinline__ unsigned int bf2pack(float lo, float hi) {
    unsigned int r;
    asm("cvt.rn.bf16x2.f32 %0, %1, %2;" : "=r"(r) : "f"(hi), "f"(lo));
    return r;
}
__device__ __forceinline__ void bfma(ull& acc, unsigned int bits, ull vv) {
    unsigned int lo = bits << 16;
    unsigned int hi = bits & 0xffff0000u;
    ull pair;
    asm("mov.b64 %0, {%1, %2};" : "=l"(pair) : "r"(lo), "r"(hi));
    acc = fma2(pair, vv, acc);
}
__device__ __forceinline__ uint32_t tf32r(float x) {
    uint32_t r;
    asm("cvt.rna.tf32.f32 %0, %1;" : "=r"(r) : "f"(x));
    return r;
}

// m16n8k8 tf32 warp MMA (baseline PTX, sm_80+)
#define MMA_TF32(c, a, b) \
    asm volatile("mma.sync.aligned.m16n8k8.row.col.f32.tf32.tf32.f32 " \
        "{%0,%1,%2,%3}, {%4,%5,%6,%7}, {%8,%9}, {%0,%1,%2,%3};" \
        : "+f"((c)[0]), "+f"((c)[1]), "+f"((c)[2]), "+f"((c)[3]) \
        : "r"((a)[0]), "r"((a)[1]), "r"((a)[2]), "r"((a)[3]), \
          "r"((b)[0]), "r"((b)[1]))

// ---------------- 1: count + E init (fp32 + bf16 shadow) ----------------
__global__ void k_count_init(const int* __restrict__ rows,
                             const float* __restrict__ ue,
                             const float* __restrict__ ie) {
    int i = blockIdx.x * blockDim.x + threadIdx.x;
    if (i < NNZ) atomicAdd(&g_deg[rows[i]], 1);
    if (i < NN * (DD / 4)) {
        int n = i >> 4;
        int c = i & 15;
        const float4* src;
        int srow;
        if (n < NU) { src = (const float4*)ue; srow = n; }
        else        { src = (const float4*)ie; srow = n - NU; }
        float4 v = src[srow * 16 + c];
        ((float4*)g_E0)[i] = v;
        ((float4*)g_alle)[n * 64 + c] = v;
        uint2 b;
        b.x = bf2pack(v.x, v.y);
        b.y = bf2pack(v.z, v.w);
        ((uint2*)g_B0)[i] = b;
    }
}

// ---------------- 2: fused scan + scatter ----------------
__global__ void k_scan_scatter(const int* __restrict__ rows,
                               const int* __restrict__ cols,
                               const float* __restrict__ vals) {
    __shared__ int s[SCAN_CHUNK];
    __shared__ int wsum[4];
    __shared__ int s_off;
    int b = blockIdx.x;
    int t = threadIdx.x;
    int i = b * SCAN_CHUNK + t;
    int v = (i < NN) ? g_deg[i] : 0;
    if (i < NN) g_deg[i] = 0;
    s[t] = v;
    __syncthreads();
    for (int off = 1; off < SCAN_CHUNK; off <<= 1) {
        int x = 0;
        if (t >= off) x = s[t - off];
        __syncthreads();
        s[t] += x;
        __syncthreads();
    }
    if (t == SCAN_CHUNK - 1) atomicExch(&g_stat[b], s[t] | STAT_READY);
    int part = 0;
    if (t < b) {
        int st;
        do { st = atomicAdd(&g_stat[t], 0); } while (!(st & STAT_READY));
        part = st & (STAT_READY - 1);
    }
    #pragma unroll
    for (int off = 16; off > 0; off >>= 1)
        part += __shfl_xor_sync(0xffffffffu, part, off);
    if ((t & 31) == 0 && (t >> 5) < 4) wsum[t >> 5] = part;
    __syncthreads();
    if (t == 0) s_off = wsum[0] + wsum[1] + wsum[2] + wsum[3];
    __syncthreads();
    int off = s_off;
    if (i < NN) {
        int incl = s[t] + off;
        g_rowptr[1 + i] = incl;
        g_cursor[i] = incl - v;
    }
    if (b == 0 && t == 0) g_rowptr[0] = 0;

    __threadfence();
    __syncthreads();
    if (t == 0) {
        atomicAdd(&g_bar, 1);
        while (atomicAdd(&g_bar, 0) < SCAN_NBLK) { }
        g_stat[b] = 0;
        int r2 = atomicAdd(&g_bar2, 1);
        if (r2 == SCAN_NBLK - 1) { g_bar = 0; g_bar2 = 0; }
    }
    __syncthreads();

    for (int e = b * SCAN_CHUNK + t; e < NNZ; e += SCAN_NBLK * SCAN_CHUNK) {
        int r = rows[e];
        int p = atomicAdd(&g_cursor[r], 1);
        int2 pr;
        pr.x = cols[e];
        pr.y = __float_as_int(vals[e]);
        g_edge[p] = pr;
    }
}

// ---------------- 3: SpMM — warp/node, bf16 rows, 4 edges per LDG.128 ----------
__global__ void __launch_bounds__(256) k_spmm(int cur) {
    const uint4* __restrict__ B4 = (const uint4*)(cur ? g_B1 : g_B0);
    __shared__ int2 sedge[8][32];
    int warp = (blockIdx.x * blockDim.x + threadIdx.x) >> 5;
    int wid  = threadIdx.x >> 5;
    int lane = threadIdx.x & 31;
    int g    = lane >> 3;
    int sub  = lane & 7;
    if (warp >= NN) return;
    int start = g_rowptr[warp];
    int end   = g_rowptr[warp + 1];
    ull a0 = 0, a1 = 0, a2 = 0, a3 = 0;
    int e0 = start;
    for (; e0 + 32 <= end; e0 += 32) {
        sedge[wid][lane] = g_edge[e0 + lane];
        __syncwarp();
        #pragma unroll
        for (int i0 = 0; i0 < 8; i0 += 4) {
            int2 eA = sedge[wid][4 * (i0 + 0) + g];
            int2 eB = sedge[wid][4 * (i0 + 1) + g];
            int2 eC = sedge[wid][4 * (i0 + 2) + g];
            int2 eD = sedge[wid][4 * (i0 + 3) + g];
            uint4 qA = B4[eA.x * 8 + sub];
            uint4 qB = B4[eB.x * 8 + sub];
            uint4 qC = B4[eC.x * 8 + sub];
            uint4 qD = B4[eD.x * 8 + sub];
            ull vA = pk2(__int_as_float(eA.y), __int_as_float(eA.y));
            ull vB = pk2(__int_as_float(eB.y), __int_as_float(eB.y));
            ull vC = pk2(__int_as_float(eC.y), __int_as_float(eC.y));
            ull vD = pk2(__int_as_float(eD.y), __int_as_float(eD.y));
            bfma(a0, qA.x, vA); bfma(a1, qA.y, vA); bfma(a2, qA.z, vA); bfma(a3, qA.w, vA);
            bfma(a0, qB.x, vB); bfma(a1, qB.y, vB); bfma(a2, qB.z, vB); bfma(a3, qB.w, vB);
            bfma(a0, qC.x, vC); bfma(a1, qC.y, vC); bfma(a2, qC.z, vC); bfma(a3, qC.w, vC);
            bfma(a0, qD.x, vD); bfma(a1, qD.y, vD); bfma(a2, qD.z, vD); bfma(a3, qD.w, vD);
        }
        __syncwarp();
    }
    int rem = end - e0;
    if (rem > 0) {
        sedge[wid][lane] = (lane < rem) ? g_edge[e0 + lane] : make_int2(0, 0);
        __syncwarp();
        int ngrp = (rem + 3) >> 2;
        for (int i = 0; i < ngrp; i++) {
            int2 ed = sedge[wid][4 * i + g];
            uint4 q = B4[ed.x * 8 + sub];
            ull vv = pk2(__int_as_float(ed.y), __int_as_float(ed.y));
            bfma(a0, q.x, vv); bfma(a1, q.y, vv); bfma(a2, q.z, vv); bfma(a3, q.w, vv);
        }
    }
    float2 f0 = upk(a0), f1 = upk(a1), f2 = upk(a2), f3 = upk(a3);
    #pragma unroll
    for (int off = 8; off <= 16; off <<= 1) {
        f0.x += __shfl_xor_sync(0xffffffffu, f0.x, off);
        f0.y += __shfl_xor_sync(0xffffffffu, f0.y, off);
        f1.x += __shfl_xor_sync(0xffffffffu, f1.x, off);
        f1.y += __shfl_xor_sync(0xffffffffu, f1.y, off);
        f2.x += __shfl_xor_sync(0xffffffffu, f2.x, off);
        f2.y += __shfl_xor_sync(0xffffffffu, f2.y, off);
        f3.x += __shfl_xor_sync(0xffffffffu, f3.x, off);
        f3.y += __shfl_xor_sync(0xffffffffu, f3.y, off);
    }
    if (lane < 8) {
        *(float4*)&g_Lmul[warp * DD + lane * 8]     = make_float4(f0.x, f0.y, f1.x, f1.y);
        *(float4*)&g_Lmul[warp * DD + lane * 8 + 4] = make_float4(f2.x, f2.y, f3.x, f3.y);
    }
}

// ---------------- 4: GEMM via mma.sync tf32 — 128 rows/block, 8 warps ---------
// R12 structure exactly (proven 53.3us); only change: last layer skips E/B stores.
#define GP 68
#define OFF_AS 0
#define OFF_RS (128 * GP)
#define OFF_W1S (2 * 128 * GP)
#define OFF_W2S (2 * 128 * GP + 64 * GP)
#define OFF_BIAS (2 * 128 * GP + 2 * 64 * GP)
#define GEMM_SMEM_FLOATS (OFF_BIAS + 64)

__global__ void __launch_bounds__(256, 2) k_gemm(int cur, int l,
                                                 const float* __restrict__ W1,
                                                 const float* __restrict__ b1,
                                                 const float* __restrict__ W2,
                                                 const float* __restrict__ b2) {
    extern __shared__ float sm[];
    uint32_t* Au  = (uint32_t*)(sm + OFF_AS);    // [128][GP] tf32 bits
    uint32_t* Ru  = (uint32_t*)(sm + OFF_RS);    // [128][GP]
    uint32_t* W1u = (uint32_t*)(sm + OFF_W1S);   // [64][GP]  W'[n][k]
    uint32_t* W2u = (uint32_t*)(sm + OFF_W2S);   // [64][GP]
    float* biasS  = sm + OFF_BIAS;

    const float*  Ecur  = cur ? g_E1 : g_E0;
    float*        Enext = cur ? g_E0 : g_E1;
    unsigned int* Bnext = cur ? g_B0 : g_B1;

    int tid  = threadIdx.x;
    int wid  = tid >> 5;
    int lane = tid & 31;
    int g    = lane >> 2;        // 0..7
    int tg   = lane & 3;         // 0..3
    int rw   = wid * 16;         // warp's m16 tile base row
    int n0 = blockIdx.x * 128;
    int lw = l * 64 * 64;
    int lb = l * 64;

    if (tid < 64) biasS[tid] = b1[lb + tid] + b2[lb + tid];

    // ---- stage A = Lmul+E, R = Lmul*E (tf32-rounded); half-row per thread ----
    {
        int row  = tid >> 1;
        int half = (tid & 1) * 8;
        int n = n0 + row;
        const float4* LM4 = (const float4*)g_Lmul;
        const float4* EC4 = (const float4*)Ecur;
        #pragma unroll
        for (int cc = 0; cc < 8; cc++) {
            int c = half + cc;
            float4 lm = make_float4(0, 0, 0, 0), ev = make_float4(0, 0, 0, 0);
            if (n < NN) {
                lm = LM4[n * 16 + c];
                ev = EC4[n * 16 + c];
            }
            uint4 av, rv;
            av.x = tf32r(lm.x + ev.x); av.y = tf32r(lm.y + ev.y);
            av.z = tf32r(lm.z + ev.z); av.w = tf32r(lm.w + ev.w);
            rv.x = tf32r(lm.x * ev.x); rv.y = tf32r(lm.y * ev.y);
            rv.z = tf32r(lm.z * ev.z); rv.w = tf32r(lm.w * ev.w);
            *(uint4*)&Au[row * GP + c * 4] = av;
            *(uint4*)&Ru[row * GP + c * 4] = rv;
        }
    }
    // ---- stage W' (transposed: W'[n][k] = W[k][n]), tf32-rounded (R12 form) ----
    {
        int j  = tid >> 2;
        int kq = (tid & 3) * 16;
        #pragma unroll
        for (int kk = 0; kk < 16; kk++) {
            int k = kq + kk;
            W1u[j * GP + k] = tf32r(W1[lw + k * 64 + j]);
            W2u[j * GP + k] = tf32r(W2[lw + k * 64 + j]);
        }
    }
    __syncthreads();

    // ---- accumulators: c[jt] covers rows {rw+g, rw+8+g}, cols {8jt+2tg, +1}
    float c[8][4];
    #pragma unroll
    for (int jt = 0; jt < 8; jt++) {
        float bv0 = biasS[8 * jt + 2 * tg];
        float bv1 = biasS[8 * jt + 2 * tg + 1];
        c[jt][0] = bv0; c[jt][1] = bv1;
        c[jt][2] = bv0; c[jt][3] = bv1;
    }

    #pragma unroll 2
    for (int kb = 0; kb < 64; kb += 8) {
        uint32_t af[4], rf[4];
        int rr = rw + g;
        af[0] = Au[rr * GP + kb + tg];
        af[1] = Au[(rr + 8) * GP + kb + tg];
        af[2] = Au[rr * GP + kb + tg + 4];
        af[3] = Au[(rr + 8) * GP + kb + tg + 4];
        rf[0] = Ru[rr * GP + kb + tg];
        rf[1] = Ru[(rr + 8) * GP + kb + tg];
        rf[2] = Ru[rr * GP + kb + tg + 4];
        rf[3] = Ru[(rr + 8) * GP + kb + tg + 4];
        #pragma unroll
        for (int jt = 0; jt < 8; jt++) {
            uint32_t w1f[2], w2f[2];
            int nn = 8 * jt + g;
            w1f[0] = W1u[nn * GP + kb + tg];
            w1f[1] = W1u[nn * GP + kb + tg + 4];
            w2f[0] = W2u[nn * GP + kb + tg];
            w2f[1] = W2u[nn * GP + kb + tg + 4];
            MMA_TF32(c[jt], af, w1f);
            MMA_TF32(c[jt], rf, w2f);
        }
    }

    // ---- leaky relu + per-row sq partials ----
    float sq[2] = {0, 0};
    #pragma unroll
    for (int jt = 0; jt < 8; jt++) {
        #pragma unroll
        for (int q = 0; q < 4; q++) {
            float v = c[jt][q];
            v = (v >= 0.0f) ? v : 0.2f * v;
            c[jt][q] = v;
            sq[q >> 1] = fmaf(v, v, sq[q >> 1]);
        }
    }
    sq[0] += __shfl_xor_sync(0xffffffffu, sq[0], 1);
    sq[0] += __shfl_xor_sync(0xffffffffu, sq[0], 2);
    sq[1] += __shfl_xor_sync(0xffffffffu, sq[1], 1);
    sq[1] += __shfl_xor_sync(0xffffffffu, sq[1], 2);

    __syncthreads();   // all fragment LDS done -> safe to reuse As/Rs
    float* OutS = sm + OFF_AS;        // [128][GP]
    float* sqS  = sm + OFF_RS;        // [128]
    {
        int rA = rw + g;
        #pragma unroll
        for (int jt = 0; jt < 8; jt++) {
            *(float2*)&OutS[rA * GP + 8 * jt + 2 * tg] =
                make_float2(c[jt][0], c[jt][1]);
            *(float2*)&OutS[(rA + 8) * GP + 8 * jt + 2 * tg] =
                make_float2(c[jt][2], c[jt][3]);
        }
        if (tg == 0) {
            sqS[rA]     = sq[0];
            sqS[rA + 8] = sq[1];
        }
    }
    __syncthreads();

    // ---- coalesced global writes (last layer: only alle is consumed) ----
    {
        int tx = tid & 15;
        int ty = tid >> 4;           // 0..15
        int colblk = (l + 1) * 64;
        #pragma unroll 4
        for (int rr = 0; rr < 8; rr++) {
            int r = ty * 8 + rr;
            int n = n0 + r;
            if (n < NN) {
                float inv = 1.0f / fmaxf(sqrtf(sqS[r]), 1e-12f);
                const float* o = &OutS[r * GP + tx * 4];
                float4 v = make_float4(o[0], o[1], o[2], o[3]);
                if (l < NLAYERS - 1) {
                    *(float4*)&Enext[n * DD + tx * 4] = v;
                    uint2 bv;
                    bv.x = bf2pack(v.x, v.y);
                    bv.y = bf2pack(v.z, v.w);
                    *(uint2*)&Bnext[n * 32 + tx * 2] = bv;
                }
                *(float4*)&g_alle[n * 256 + colblk + tx * 4] =
                    make_float4(v.x * inv, v.y * inv, v.z * inv, v.w * inv);
            }
        }
    }
}

// ---------------- 5: loss + fused finalize ----------------
__global__ void k_loss(const int* __restrict__ users,
                       const int* __restrict__ pos,
                       const int* __restrict__ neg,
                       float* __restrict__ out) {
    int warp = (blockIdx.x * blockDim.x + threadIdx.x) >> 5;
    int lane = threadIdx.x & 31;
    if (warp < NB) {
        int uu = users[warp];
        int pp = pos[warp];
        int nn = neg[warp];
        const float4* A4 = (const float4*)g_alle;
        float pd = 0, nd = 0, su = 0, sp = 0, sn = 0;
        #pragma unroll
        for (int t = 0; t < 2; t++) {
            float4 u = A4[uu * 64 + lane * 2 + t];
            float4 p = A4[pp * 64 + lane * 2 + t];
            float4 q = A4[nn * 64 + lane * 2 + t];
            pd += u.x * p.x + u.y * p.y + u.z * p.z + u.w * p.w;
            nd += u.x * q.x + u.y * q.y + u.z * q.z + u.w * q.w;
            su += u.x * u.x + u.y * u.y + u.z * u.z + u.w * u.w;
            sp += p.x * p.x + p.y * p.y + p.z * p.z + p.w * p.w;
            sn += q.x * q.x + q.y * q.y + q.z * q.z + q.w * q.w;
        }
        #pragma unroll
        for (int off = 16; off > 0; off >>= 1) {
            pd += __shfl_xor_sync(0xffffffffu, pd, off);
            nd += __shfl_xor_sync(0xffffffffu, nd, off);
            su += __shfl_xor_sync(0xffffffffu, su, off);
            sp += __shfl_xor_sync(0xffffffffu, sp, off);
            sn += __shfl_xor_sync(0xffffffffu, sn, off);
        }
        if (lane == 0) {
            float d = pd - nd;
            float ls = fminf(d, 0.0f) - log1pf(expf(-fabsf(d)));
            atomicAdd(&g_acc[0], ls);
            atomicAdd(&g_acc[1], su);
            atomicAdd(&g_acc[2], sp);
            atomicAdd(&g_acc[3], sn);
        }
    }
    __threadfence();
    __syncthreads();
    if (threadIdx.x == 0) {
        int r = atomicAdd(&g_done, 1);
        if (r == LOSS_NBLK - 1) {
            float a0 = atomicAdd(&g_acc[0], 0.0f);
            float a1 = atomicAdd(&g_acc[1], 0.0f);
            float a2 = atomicAdd(&g_acc[2], 0.0f);
            float a3 = atomicAdd(&g_acc[3], 0.0f);
            float bpr = -a0 / (float)NB;
            float l2norm = (a1 + a2 + sqrtf(a3)) * 0.5f;
            out[0] = bpr + L2_REG * l2norm / (float)NB;
            g_acc[0] = 0.0f; g_acc[1] = 0.0f; g_acc[2] = 0.0f; g_acc[3] = 0.0f;
            g_done = 0;
        }
    }
}

// ---------------- launch ----------------
extern "C" void kernel_launch(void* const* d_in, const int* in_sizes, int n_in,
                              void* d_out, int out_size) {
    const int*   users = (const int*)d_in[0];
    const int*   pos   = (const int*)d_in[1];
    const int*   neg   = (const int*)d_in[2];
    const int*   rows  = (const int*)d_in[3];
    const int*   cols  = (const int*)d_in[4];
    const float* vals  = (const float*)d_in[5];
    const float* ue    = (const float*)d_in[6];
    const float* ie    = (const float*)d_in[7];
    const float* W1    = (const float*)d_in[8];
    const float* b1    = (const float*)d_in[9];
    const float* W2    = (const float*)d_in[10];
    const float* b2    = (const float*)d_in[11];
    float* out = (float*)d_out;

    cudaFuncSetAttribute(k_gemm, cudaFuncAttributeMaxDynamicSharedMemorySize,
                         GEMM_SMEM_FLOATS * sizeof(float));

    k_count_init<<<(NNZ + 255) / 256, 256>>>(rows, ue, ie);
    k_scan_scatter<<<SCAN_NBLK, SCAN_CHUNK>>>(rows, cols, vals);

    int cur = 0;
    for (int l = 0; l < NLAYERS; l++) {
        k_spmm<<<(NN + 7) / 8, 256>>>(cur);
        k_gemm<<<(NN + 127) / 128, 256, GEMM_SMEM_FLOATS * sizeof(float)>>>(
            cur, l, W1, b1, W2, b2);
        cur ^= 1;
    }

    k_loss<<<LOSS_NBLK, 256>>>(users, pos, neg, out);
}

// round 16
// speedup vs baseline: 1.3028x; 1.0210x over previous
#include <cuda_runtime.h>
#include <math.h>
#include <stdint.h>

// Problem constants
#define NU 50000
#define NI 50000
#define NN 100000          // NU + NI
#define DD 64
#define NNZ 3200000
#define NLAYERS 3
#define NB 4096
#define L2_REG 1e-5f

#define SCAN_CHUNK 1024
#define SCAN_NBLK ((NN + SCAN_CHUNK - 1) / SCAN_CHUNK)   // 98
#define STAT_READY (1 << 30)
#define LOSS_NBLK (NB / 8)                               // 512 blocks of 8 warps

// ---------------- device scratch (no allocs allowed) ----------------
__device__ __align__(256) float g_E0[NN * DD];
__device__ __align__(256) float g_E1[NN * DD];
__device__ __align__(256) unsigned int g_B0[NN * 32];   // bf16x2 shadow of E0
__device__ __align__(256) unsigned int g_B1[NN * 32];   // bf16x2 shadow of E1
__device__ __align__(256) float g_Lmul[NN * DD];
__device__ __align__(256) float g_alle[NN * DD * (NLAYERS + 1)];   // [N, 256]
__device__ unsigned char g_need[NN];   // set-only sampled-node flags (idempotent)
__device__ int   g_deg[NN];
__device__ int   g_rowptr[NN + 1];
__device__ int   g_cursor[NN];
__device__ __align__(16) int2 g_edge[NNZ];
__device__ int   g_stat[SCAN_NBLK];
__device__ int   g_bar;
__device__ int   g_bar2;
__device__ int   g_done;
__device__ float g_acc[4];

// ---------------- helpers ----------------
typedef unsigned long long ull;

__device__ __forceinline__ ull fma2(ull a, ull b, ull c) {
    ull d;
    asm("fma.rn.f32x2 %0, %1, %2, %3;" : "=l"(d) : "l"(a), "l"(b), "l"(c));
    return d;
}
__device__ __forceinline__ ull pk2(float lo, float hi) {
    ull d;
    asm("mov.b64 %0, {%1, %2};" : "=l"(d) : "f"(lo), "f"(hi));
    return d;
}
__device__ __forceinline__ float2 upk(ull v) {
    float2 f;
    asm("mov.b64 {%0, %1}, %2;" : "=f"(f.x), "=f"(f.y) : "l"(v));
    return f;
}
__device__ __forceinline__ unsigned int bf2pack(float lo, float hi) {
    unsigned int r;
    asm("cvt.rn.bf16x2.f32 %0, %1, %2;" : "=r"(r) : "f"(hi), "f"(lo));
    return r;
}
__device__ __forceinline__ void bfma(ull& acc, unsigned int bits, ull vv) {
    unsigned int lo = bits << 16;
    unsigned int hi = bits & 0xffff0000u;
    ull pair;
    asm("mov.b64 %0, {%1, %2};" : "=l"(pair) : "r"(lo), "r"(hi));
    acc = fma2(pair, vv, acc);
}
__device__ __forceinline__ uint32_t tf32r(float x) {
    uint32_t r;
    asm("cvt.rna.tf32.f32 %0, %1;" : "=r"(r) : "f"(x));
    return r;
}

// m16n8k8 tf32 warp MMA (baseline PTX, sm_80+)
#define MMA_TF32(c, a, b) \
    asm volatile("mma.sync.aligned.m16n8k8.row.col.f32.tf32.tf32.f32 " \
        "{%0,%1,%2,%3}, {%4,%5,%6,%7}, {%8,%9}, {%0,%1,%2,%3};" \
        : "+f"((c)[0]), "+f"((c)[1]), "+f"((c)[2]), "+f"((c)[3]) \
        : "r"((a)[0]), "r"((a)[1]), "r"((a)[2]), "r"((a)[3]), \
          "r"((b)[0]), "r"((b)[1]))

// ---------------- 0: mark sampled nodes (set-only -> replay-safe) ----------------
__global__ void k_mark(const int* __restrict__ users,
                       const int* __restrict__ pos,
                       const int* __restrict__ neg) {
    int i = blockIdx.x * blockDim.x + threadIdx.x;
    if (i < NB) {
        g_need[users[i]] = 1;
        g_need[pos[i]]   = 1;
        g_need[neg[i]]   = 1;
    }
}

// ---------------- 1: count + E init (fp32 + bf16 shadow; alle gated) -----------
__global__ void k_count_init(const int* __restrict__ rows,
                             const float* __restrict__ ue,
                             const float* __restrict__ ie) {
    int i = blockIdx.x * blockDim.x + threadIdx.x;
    if (i < NNZ) atomicAdd(&g_deg[rows[i]], 1);
    if (i < NN * (DD / 4)) {
        int n = i >> 4;
        int c = i & 15;
        const float4* src;
        int srow;
        if (n < NU) { src = (const float4*)ue; srow = n; }
        else        { src = (const float4*)ie; srow = n - NU; }
        float4 v = src[srow * 16 + c];
        ((float4*)g_E0)[i] = v;
        if (g_need[n]) ((float4*)g_alle)[n * 64 + c] = v;
        uint2 b;
        b.x = bf2pack(v.x, v.y);
        b.y = bf2pack(v.z, v.w);
        ((uint2*)g_B0)[i] = b;
    }
}

// ---------------- 2: fused scan + scatter ----------------
__global__ void k_scan_scatter(const int* __restrict__ rows,
                               const int* __restrict__ cols,
                               const float* __restrict__ vals) {
    __shared__ int s[SCAN_CHUNK];
    __shared__ int wsum[4];
    __shared__ int s_off;
    int b = blockIdx.x;
    int t = threadIdx.x;
    int i = b * SCAN_CHUNK + t;
    int v = (i < NN) ? g_deg[i] : 0;
    if (i < NN) g_deg[i] = 0;
    s[t] = v;
    __syncthreads();
    for (int off = 1; off < SCAN_CHUNK; off <<= 1) {
        int x = 0;
        if (t >= off) x = s[t - off];
        __syncthreads();
        s[t] += x;
        __syncthreads();
    }
    if (t == SCAN_CHUNK - 1) atomicExch(&g_stat[b], s[t] | STAT_READY);
    int part = 0;
    if (t < b) {
        int st;
        do { st = atomicAdd(&g_stat[t], 0); } while (!(st & STAT_READY));
        part = st & (STAT_READY - 1);
    }
    #pragma unroll
    for (int off = 16; off > 0; off >>= 1)
        part += __shfl_xor_sync(0xffffffffu, part, off);
    if ((t & 31) == 0 && (t >> 5) < 4) wsum[t >> 5] = part;
    __syncthreads();
    if (t == 0) s_off = wsum[0] + wsum[1] + wsum[2] + wsum[3];
    __syncthreads();
    int off = s_off;
    if (i < NN) {
        int incl = s[t] + off;
        g_rowptr[1 + i] = incl;
        g_cursor[i] = incl - v;
    }
    if (b == 0 && t == 0) g_rowptr[0] = 0;

    __threadfence();
    __syncthreads();
    if (t == 0) {
        atomicAdd(&g_bar, 1);
        while (atomicAdd(&g_bar, 0) < SCAN_NBLK) { }
        g_stat[b] = 0;
        int r2 = atomicAdd(&g_bar2, 1);
        if (r2 == SCAN_NBLK - 1) { g_bar = 0; g_bar2 = 0; }
    }
    __syncthreads();

    for (int e = b * SCAN_CHUNK + t; e < NNZ; e += SCAN_NBLK * SCAN_CHUNK) {
        int r = rows[e];
        int p = atomicAdd(&g_cursor[r], 1);
        int2 pr;
        pr.x = cols[e];
        pr.y = __float_as_int(vals[e]);
        g_edge[p] = pr;
    }
}

// ---------------- 3: SpMM — warp/node, bf16 rows, 4 edges per LDG.128 ----------
__global__ void __launch_bounds__(256) k_spmm(int cur) {
    const uint4* __restrict__ B4 = (const uint4*)(cur ? g_B1 : g_B0);
    __shared__ int2 sedge[8][32];
    int warp = (blockIdx.x * blockDim.x + threadIdx.x) >> 5;
    int wid  = threadIdx.x >> 5;
    int lane = threadIdx.x & 31;
    int g    = lane >> 3;
    int sub  = lane & 7;
    if (warp >= NN) return;
    int start = g_rowptr[warp];
    int end   = g_rowptr[warp + 1];
    ull a0 = 0, a1 = 0, a2 = 0, a3 = 0;
    int e0 = start;
    for (; e0 + 32 <= end; e0 += 32) {
        sedge[wid][lane] = g_edge[e0 + lane];
        __syncwarp();
        #pragma unroll
        for (int i0 = 0; i0 < 8; i0 += 4) {
            int2 eA = sedge[wid][4 * (i0 + 0) + g];
            int2 eB = sedge[wid][4 * (i0 + 1) + g];
            int2 eC = sedge[wid][4 * (i0 + 2) + g];
            int2 eD = sedge[wid][4 * (i0 + 3) + g];
            uint4 qA = B4[eA.x * 8 + sub];
            uint4 qB = B4[eB.x * 8 + sub];
            uint4 qC = B4[eC.x * 8 + sub];
            uint4 qD = B4[eD.x * 8 + sub];
            ull vA = pk2(__int_as_float(eA.y), __int_as_float(eA.y));
            ull vB = pk2(__int_as_float(eB.y), __int_as_float(eB.y));
            ull vC = pk2(__int_as_float(eC.y), __int_as_float(eC.y));
            ull vD = pk2(__int_as_float(eD.y), __int_as_float(eD.y));
            bfma(a0, qA.x, vA); bfma(a1, qA.y, vA); bfma(a2, qA.z, vA); bfma(a3, qA.w, vA);
            bfma(a0, qB.x, vB); bfma(a1, qB.y, vB); bfma(a2, qB.z, vB); bfma(a3, qB.w, vB);
            bfma(a0, qC.x, vC); bfma(a1, qC.y, vC); bfma(a2, qC.z, vC); bfma(a3, qC.w, vC);
            bfma(a0, qD.x, vD); bfma(a1, qD.y, vD); bfma(a2, qD.z, vD); bfma(a3, qD.w, vD);
        }
        __syncwarp();
    }
    int rem = end - e0;
    if (rem > 0) {
        sedge[wid][lane] = (lane < rem) ? g_edge[e0 + lane] : make_int2(0, 0);
        __syncwarp();
        int ngrp = (rem + 3) >> 2;
        for (int i = 0; i < ngrp; i++) {
            int2 ed = sedge[wid][4 * i + g];
            uint4 q = B4[ed.x * 8 + sub];
            ull vv = pk2(__int_as_float(ed.y), __int_as_float(ed.y));
            bfma(a0, q.x, vv); bfma(a1, q.y, vv); bfma(a2, q.z, vv); bfma(a3, q.w, vv);
        }
    }
    float2 f0 = upk(a0), f1 = upk(a1), f2 = upk(a2), f3 = upk(a3);
    #pragma unroll
    for (int off = 8; off <= 16; off <<= 1) {
        f0.x += __shfl_xor_sync(0xffffffffu, f0.x, off);
        f0.y += __shfl_xor_sync(0xffffffffu, f0.y, off);
        f1.x += __shfl_xor_sync(0xffffffffu, f1.x, off);
        f1.y += __shfl_xor_sync(0xffffffffu, f1.y, off);
        f2.x += __shfl_xor_sync(0xffffffffu, f2.x, off);
        f2.y += __shfl_xor_sync(0xffffffffu, f2.y, off);
        f3.x += __shfl_xor_sync(0xffffffffu, f3.x, off);
        f3.y += __shfl_xor_sync(0xffffffffu, f3.y, off);
    }
    if (lane < 8) {
        *(float4*)&g_Lmul[warp * DD + lane * 8]     = make_float4(f0.x, f0.y, f1.x, f1.y);
        *(float4*)&g_Lmul[warp * DD + lane * 8 + 4] = make_float4(f2.x, f2.y, f3.x, f3.y);
    }
}

// ---------------- 4: GEMM via mma.sync tf32 — 128 rows/block, 8 warps ---------
// R12 structure; last layer skips E/B stores; alle writes gated by g_need.
#define GP 68
#define OFF_AS 0
#define OFF_RS (128 * GP)
#define OFF_W1S (2 * 128 * GP)
#define OFF_W2S (2 * 128 * GP + 64 * GP)
#define OFF_BIAS (2 * 128 * GP + 2 * 64 * GP)
#define GEMM_SMEM_FLOATS (OFF_BIAS + 64)

__global__ void __launch_bounds__(256, 2) k_gemm(int cur, int l,
                                                 const float* __restrict__ W1,
                                                 const float* __restrict__ b1,
                                                 const float* __restrict__ W2,
                                                 const float* __restrict__ b2) {
    extern __shared__ float sm[];
    uint32_t* Au  = (uint32_t*)(sm + OFF_AS);    // [128][GP] tf32 bits
    uint32_t* Ru  = (uint32_t*)(sm + OFF_RS);    // [128][GP]
    uint32_t* W1u = (uint32_t*)(sm + OFF_W1S);   // [64][GP]  W'[n][k]
    uint32_t* W2u = (uint32_t*)(sm + OFF_W2S);   // [64][GP]
    float* biasS  = sm + OFF_BIAS;

    const float*  Ecur  = cur ? g_E1 : g_E0;
    float*        Enext = cur ? g_E0 : g_E1;
    unsigned int* Bnext = cur ? g_B0 : g_B1;

    int tid  = threadIdx.x;
    int wid  = tid >> 5;
    int lane = tid & 31;
    int g    = lane >> 2;        // 0..7
    int tg   = lane & 3;         // 0..3
    int rw   = wid * 16;         // warp's m16 tile base row
    int n0 = blockIdx.x * 128;
    int lw = l * 64 * 64;
    int lb = l * 64;

    if (tid < 64) biasS[tid] = b1[lb + tid] + b2[lb + tid];

    // ---- stage A = Lmul+E, R = Lmul*E (tf32-rounded); half-row per thread ----
    {
        int row  = tid >> 1;
        int half = (tid & 1) * 8;
        int n = n0 + row;
        const float4* LM4 = (const float4*)g_Lmul;
        const float4* EC4 = (const float4*)Ecur;
        #pragma unroll
        for (int cc = 0; cc < 8; cc++) {
            int c = half + cc;
            float4 lm = make_float4(0, 0, 0, 0), ev = make_float4(0, 0, 0, 0);
            if (n < NN) {
                lm = LM4[n * 16 + c];
                ev = EC4[n * 16 + c];
            }
            uint4 av, rv;
            av.x = tf32r(lm.x + ev.x); av.y = tf32r(lm.y + ev.y);
            av.z = tf32r(lm.z + ev.z); av.w = tf32r(lm.w + ev.w);
            rv.x = tf32r(lm.x * ev.x); rv.y = tf32r(lm.y * ev.y);
            rv.z = tf32r(lm.z * ev.z); rv.w = tf32r(lm.w * ev.w);
            *(uint4*)&Au[row * GP + c * 4] = av;
            *(uint4*)&Ru[row * GP + c * 4] = rv;
        }
    }
    // ---- stage W' (transposed: W'[n][k] = W[k][n]), tf32-rounded ----
    {
        int j  = tid >> 2;
        int kq = (tid & 3) * 16;
        #pragma unroll
        for (int kk = 0; kk < 16; kk++) {
            int k = kq + kk;
            W1u[j * GP + k] = tf32r(W1[lw + k * 64 + j]);
            W2u[j * GP + k] = tf32r(W2[lw + k * 64 + j]);
        }
    }
    __syncthreads();

    // ---- accumulators: c[jt] covers rows {rw+g, rw+8+g}, cols {8jt+2tg, +1}
    float c[8][4];
    #pragma unroll
    for (int jt = 0; jt < 8; jt++) {
        float bv0 = biasS[8 * jt + 2 * tg];
        float bv1 = biasS[8 * jt + 2 * tg + 1];
        c[jt][0] = bv0; c[jt][1] = bv1;
        c[jt][2] = bv0; c[jt][3] = bv1;
    }

    #pragma unroll 2
    for (int kb = 0; kb < 64; kb += 8) {
        uint32_t af[4], rf[4];
        int rr = rw + g;
        af[0] = Au[rr * GP + kb + tg];
        af[1] = Au[(rr + 8) * GP + kb + tg];
        af[2] = Au[rr * GP + kb + tg + 4];
        af[3] = Au[(rr + 8) * GP + kb + tg + 4];
        rf[0] = Ru[rr * GP + kb + tg];
        rf[1] = Ru[(rr + 8) * GP + kb + tg];
        rf[2] = Ru[rr * GP + kb + tg + 4];
        rf[3] = Ru[(rr + 8) * GP + kb + tg + 4];
        #pragma unroll
        for (int jt = 0; jt < 8; jt++) {
            uint32_t w1f[2], w2f[2];
            int nn = 8 * jt + g;
            w1f[0] = W1u[nn * GP + kb + tg];
            w1f[1] = W1u[nn * GP + kb + tg + 4];
            w2f[0] = W2u[nn * GP + kb + tg];
            w2f[1] = W2u[nn * GP + kb + tg + 4];
            MMA_TF32(c[jt], af, w1f);
            MMA_TF32(c[jt], rf, w2f);
        }
    }

    // ---- leaky relu + per-row sq partials ----
    float sq[2] = {0, 0};
    #pragma unroll
    for (int jt = 0; jt < 8; jt++) {
        #pragma unroll
        for (int q = 0; q < 4; q++) {
            float v = c[jt][q];
            v = (v >= 0.0f) ? v : 0.2f * v;
            c[jt][q] = v;
            sq[q >> 1] = fmaf(v, v, sq[q >> 1]);
        }
    }
    sq[0] += __shfl_xor_sync(0xffffffffu, sq[0], 1);
    sq[0] += __shfl_xor_sync(0xffffffffu, sq[0], 2);
    sq[1] += __shfl_xor_sync(0xffffffffu, sq[1], 1);
    sq[1] += __shfl_xor_sync(0xffffffffu, sq[1], 2);

    __syncthreads();   // all fragment LDS done -> safe to reuse As/Rs
    float* OutS = sm + OFF_AS;        // [128][GP]
    float* sqS  = sm + OFF_RS;        // [128]
    {
        int rA = rw + g;
        #pragma unroll
        for (int jt = 0; jt < 8; jt++) {
            *(float2*)&OutS[rA * GP + 8 * jt + 2 * tg] =
                make_float2(c[jt][0], c[jt][1]);
            *(float2*)&OutS[(rA + 8) * GP + 8 * jt + 2 * tg] =
                make_float2(c[jt][2], c[jt][3]);
        }
        if (tg == 0) {
            sqS[rA]     = sq[0];
            sqS[rA + 8] = sq[1];
        }
    }
    __syncthreads();

    // ---- coalesced global writes (E/B only if consumed; alle only if sampled) --
    {
        int tx = tid & 15;
        int ty = tid >> 4;           // 0..15
        int colblk = (l + 1) * 64;
        #pragma unroll 4
        for (int rr = 0; rr < 8; rr++) {
            int r = ty * 8 + rr;
            int n = n0 + r;
            if (n < NN) {
                const float* o = &OutS[r * GP + tx * 4];
                float4 v = make_float4(o[0], o[1], o[2], o[3]);
                if (l < NLAYERS - 1) {
                    *(float4*)&Enext[n * DD + tx * 4] = v;
                    uint2 bv;
                    bv.x = bf2pack(v.x, v.y);
                    bv.y = bf2pack(v.z, v.w);
                    *(uint2*)&Bnext[n * 32 + tx * 2] = bv;
                }
                if (g_need[n]) {
                    float inv = 1.0f / fmaxf(sqrtf(sqS[r]), 1e-12f);
                    *(float4*)&g_alle[n * 256 + colblk + tx * 4] =
                        make_float4(v.x * inv, v.y * inv, v.z * inv, v.w * inv);
                }
            }
        }
    }
}

// ---------------- 5: loss + fused finalize ----------------
__global__ void k_loss(const int* __restrict__ users,
                       const int* __restrict__ pos,
                       const int* __restrict__ neg,
                       float* __restrict__ out) {
    int warp = (blockIdx.x * blockDim.x + threadIdx.x) >> 5;
    int lane = threadIdx.x & 31;
    if (warp < NB) {
        int uu = users[warp];
        int pp = pos[warp];
        int nn = neg[warp];
        const float4* A4 = (const float4*)g_alle;
        float pd = 0, nd = 0, su = 0, sp = 0, sn = 0;
        #pragma unroll
        for (int t = 0; t < 2; t++) {
            float4 u = A4[uu * 64 + lane * 2 + t];
            float4 p = A4[pp * 64 + lane * 2 + t];
            float4 q = A4[nn * 64 + lane * 2 + t];
            pd += u.x * p.x + u.y * p.y + u.z * p.z + u.w * p.w;
            nd += u.x * q.x + u.y * q.y + u.z * q.z + u.w * q.w;
            su += u.x * u.x + u.y * u.y + u.z * u.z + u.w * u.w;
            sp += p.x * p.x + p.y * p.y + p.z * p.z + p.w * p.w;
            sn += q.x * q.x + q.y * q.y + q.z * q.z + q.w * q.w;
        }
        #pragma unroll
        for (int off = 16; off > 0; off >>= 1) {
            pd += __shfl_xor_sync(0xffffffffu, pd, off);
            nd += __shfl_xor_sync(0xffffffffu, nd, off);
            su += __shfl_xor_sync(0xffffffffu, su, off);
            sp += __shfl_xor_sync(0xffffffffu, sp, off);
            sn += __shfl_xor_sync(0xffffffffu, sn, off);
        }
        if (lane == 0) {
            float d = pd - nd;
            float ls = fminf(d, 0.0f) - log1pf(expf(-fabsf(d)));
            atomicAdd(&g_acc[0], ls);
            atomicAdd(&g_acc[1], su);
            atomicAdd(&g_acc[2], sp);
            atomicAdd(&g_acc[3], sn);
        }
    }
    __threadfence();
    __syncthreads();
    if (threadIdx.x == 0) {
        int r = atomicAdd(&g_done, 1);
        if (r == LOSS_NBLK - 1) {
            float a0 = atomicAdd(&g_acc[0], 0.0f);
            float a1 = atomicAdd(&g_acc[1], 0.0f);
            float a2 = atomicAdd(&g_acc[2], 0.0f);
            float a3 = atomicAdd(&g_acc[3], 0.0f);
            float bpr = -a0 / (float)NB;
            float l2norm = (a1 + a2 + sqrtf(a3)) * 0.5f;
            out[0] = bpr + L2_REG * l2norm / (float)NB;
            g_acc[0] = 0.0f; g_acc[1] = 0.0f; g_acc[2] = 0.0f; g_acc[3] = 0.0f;
            g_done = 0;
        }
    }
}

// ---------------- launch ----------------
extern "C" void kernel_launch(void* const* d_in, const int* in_sizes, int n_in,
                              void* d_out, int out_size) {
    const int*   users = (const int*)d_in[0];
    const int*   pos   = (const int*)d_in[1];
    const int*   neg   = (const int*)d_in[2];
    const int*   rows  = (const int*)d_in[3];
    const int*   cols  = (const int*)d_in[4];
    const float* vals  = (const float*)d_in[5];
    const float* ue    = (const float*)d_in[6];
    const float* ie    = (const float*)d_in[7];
    const float* W1    = (const float*)d_in[8];
    const float* b1    = (const float*)d_in[9];
    const float* W2    = (const float*)d_in[10];
    const float* b2    = (const float*)d_in[11];
    float* out = (float*)d_out;

    cudaFuncSetAttribute(k_gemm, cudaFuncAttributeMaxDynamicSharedMemorySize,
                         GEMM_SMEM_FLOATS * sizeof(float));

    // 0: mark sampled nodes (before anything reads g_need)
    k_mark<<<(NB + 255) / 256, 256>>>(users, pos, neg);
    // 1: count + E init
    k_count_init<<<(NNZ + 255) / 256, 256>>>(rows, ue, ie);
    // 2: fused scan + scatter
    k_scan_scatter<<<SCAN_NBLK, SCAN_CHUNK>>>(rows, cols, vals);

    int cur = 0;
    for (int l = 0; l < NLAYERS; l++) {
        k_spmm<<<(NN + 7) / 8, 256>>>(cur);
        k_gemm<<<(NN + 127) / 128, 256, GEMM_SMEM_FLOATS * sizeof(float)>>>(
            cur, l, W1, b1, W2, b2);
        cur ^= 1;
    }

    k_loss<<<LOSS_NBLK, 256>>>(users, pos, neg, out);
}

// round 17
// speedup vs baseline: 1.5663x; 1.2022x over previous
#include <cuda_runtime.h>
#include <math.h>
#include <stdint.h>

// Problem constants
#define NU 50000
#define NI 50000
#define NN 100000          // NU + NI
#define DD 64
#define NNZ 3200000
#define NLAYERS 3
#define NB 4096
#define L2_REG 1e-5f

#define SCAN_CHUNK 1024
#define SCAN_NBLK ((NN + SCAN_CHUNK - 1) / SCAN_CHUNK)   // 98
#define STAT_READY (1 << 30)
#define LOSS_NBLK (NB / 8)                               // 512 blocks of 8 warps
#define LIST_MAX (3 * NB)                                // 12288 max sampled nodes

// ---------------- device scratch (no allocs allowed) ----------------
__device__ __align__(256) float g_E0[NN * DD];
__device__ __align__(256) float g_E1[NN * DD];
__device__ __align__(256) unsigned int g_B0[NN * 32];   // bf16x2 shadow of E0
__device__ __align__(256) unsigned int g_B1[NN * 32];   // bf16x2 shadow of E1
__device__ __align__(256) float g_Lmul[NN * DD];
__device__ __align__(256) float g_alle[NN * DD * (NLAYERS + 1)];   // [N, 256]
__device__ int   g_need[NN];           // set-only sampled flags (idempotent)
__device__ int   g_list[LIST_MAX];     // compacted sampled-node ids
__device__ int   g_nlist;              // count (stable after first call)
__device__ int   g_deg[NN];
__device__ int   g_rowptr[NN + 1];
__device__ int   g_cursor[NN];
__device__ __align__(16) int2 g_edge[NNZ];
__device__ int   g_stat[SCAN_NBLK];
__device__ int   g_bar;
__device__ int   g_bar2;
__device__ int   g_done;
__device__ float g_acc[4];

// ---------------- helpers ----------------
typedef unsigned long long ull;

__device__ __forceinline__ ull fma2(ull a, ull b, ull c) {
    ull d;
    asm("fma.rn.f32x2 %0, %1, %2, %3;" : "=l"(d) : "l"(a), "l"(b), "l"(c));
    return d;
}
__device__ __forceinline__ ull pk2(float lo, float hi) {
    ull d;
    asm("mov.b64 %0, {%1, %2};" : "=l"(d) : "f"(lo), "f"(hi));
    return d;
}
__device__ __forceinline__ float2 upk(ull v) {
    float2 f;
    asm("mov.b64 {%0, %1}, %2;" : "=f"(f.x), "=f"(f.y) : "l"(v));
    return f;
}
__device__ __forceinline__ unsigned int bf2pack(float lo, float hi) {
    unsigned int r;
    asm("cvt.rn.bf16x2.f32 %0, %1, %2;" : "=r"(r) : "f"(hi), "f"(lo));
    return r;
}
__device__ __forceinline__ void bfma(ull& acc, unsigned int bits, ull vv) {
    unsigned int lo = bits << 16;
    unsigned int hi = bits & 0xffff0000u;
    ull pair;
    asm("mov.b64 %0, {%1, %2};" : "=l"(pair) : "r"(lo), "r"(hi));
    acc = fma2(pair, vv, acc);
}
__device__ __forceinline__ uint32_t tf32r(float x) {
    uint32_t r;
    asm("cvt.rna.tf32.f32 %0, %1;" : "=r"(r) : "f"(x));
    return r;
}

// m16n8k8 tf32 warp MMA (baseline PTX, sm_80+)
#define MMA_TF32(c, a, b) \
    asm volatile("mma.sync.aligned.m16n8k8.row.col.f32.tf32.tf32.f32 " \
        "{%0,%1,%2,%3}, {%4,%5,%6,%7}, {%8,%9}, {%0,%1,%2,%3};" \
        : "+f"((c)[0]), "+f"((c)[1]), "+f"((c)[2]), "+f"((c)[3]) \
        : "r"((a)[0]), "r"((a)[1]), "r"((a)[2]), "r"((a)[3]), \
          "r"((b)[0]), "r"((b)[1]))

// ---------------- 0: mark sampled nodes + build compacted list ----------------
__device__ __forceinline__ void mark_node(int id) {
    if (atomicExch(&g_need[id], 1) == 0) {
        int p = atomicAdd(&g_nlist, 1);
        g_list[p] = id;
    }
}
__global__ void k_mark(const int* __restrict__ users,
                       const int* __restrict__ pos,
                       const int* __restrict__ neg) {
    int i = blockIdx.x * blockDim.x + threadIdx.x;
    if (i < NB) {
        mark_node(users[i]);
        mark_node(pos[i]);
        mark_node(neg[i]);
    }
}

// ---------------- 1: count + E init (fp32 + bf16 shadow; alle gated) -----------
__global__ void k_count_init(const int* __restrict__ rows,
                             const float* __restrict__ ue,
                             const float* __restrict__ ie) {
    int i = blockIdx.x * blockDim.x + threadIdx.x;
    if (i < NNZ) atomicAdd(&g_deg[rows[i]], 1);
    if (i < NN * (DD / 4)) {
        int n = i >> 4;
        int c = i & 15;
        const float4* src;
        int srow;
        if (n < NU) { src = (const float4*)ue; srow = n; }
        else        { src = (const float4*)ie; srow = n - NU; }
        float4 v = src[srow * 16 + c];
        ((float4*)g_E0)[i] = v;
        if (g_need[n]) ((float4*)g_alle)[n * 64 + c] = v;
        uint2 b;
        b.x = bf2pack(v.x, v.y);
        b.y = bf2pack(v.z, v.w);
        ((uint2*)g_B0)[i] = b;
    }
}

// ---------------- 2: fused scan + scatter ----------------
__global__ void k_scan_scatter(const int* __restrict__ rows,
                               const int* __restrict__ cols,
                               const float* __restrict__ vals) {
    __shared__ int s[SCAN_CHUNK];
    __shared__ int wsum[4];
    __shared__ int s_off;
    int b = blockIdx.x;
    int t = threadIdx.x;
    int i = b * SCAN_CHUNK + t;
    int v = (i < NN) ? g_deg[i] : 0;
    if (i < NN) g_deg[i] = 0;
    s[t] = v;
    __syncthreads();
    for (int off = 1; off < SCAN_CHUNK; off <<= 1) {
        int x = 0;
        if (t >= off) x = s[t - off];
        __syncthreads();
        s[t] += x;
        __syncthreads();
    }
    if (t == SCAN_CHUNK - 1) atomicExch(&g_stat[b], s[t] | STAT_READY);
    int part = 0;
    if (t < b) {
        int st;
        do { st = atomicAdd(&g_stat[t], 0); } while (!(st & STAT_READY));
        part = st & (STAT_READY - 1);
    }
    #pragma unroll
    for (int off = 16; off > 0; off >>= 1)
        part += __shfl_xor_sync(0xffffffffu, part, off);
    if ((t & 31) == 0 && (t >> 5) < 4) wsum[t >> 5] = part;
    __syncthreads();
    if (t == 0) s_off = wsum[0] + wsum[1] + wsum[2] + wsum[3];
    __syncthreads();
    int off = s_off;
    if (i < NN) {
        int incl = s[t] + off;
        g_rowptr[1 + i] = incl;
        g_cursor[i] = incl - v;
    }
    if (b == 0 && t == 0) g_rowptr[0] = 0;

    __threadfence();
    __syncthreads();
    if (t == 0) {
        atomicAdd(&g_bar, 1);
        while (atomicAdd(&g_bar, 0) < SCAN_NBLK) { }
        g_stat[b] = 0;
        int r2 = atomicAdd(&g_bar2, 1);
        if (r2 == SCAN_NBLK - 1) { g_bar = 0; g_bar2 = 0; }
    }
    __syncthreads();

    for (int e = b * SCAN_CHUNK + t; e < NNZ; e += SCAN_NBLK * SCAN_CHUNK) {
        int r = rows[e];
        int p = atomicAdd(&g_cursor[r], 1);
        int2 pr;
        pr.x = cols[e];
        pr.y = __float_as_int(vals[e]);
        g_edge[p] = pr;
    }
}

// ---------------- 3: SpMM — warp/node, bf16 rows; optional sampled-list mode ---
__global__ void __launch_bounds__(256) k_spmm(int cur, int uselist) {
    const uint4* __restrict__ B4 = (const uint4*)(cur ? g_B1 : g_B0);
    __shared__ int2 sedge[8][32];
    int warp = (blockIdx.x * blockDim.x + threadIdx.x) >> 5;
    int wid  = threadIdx.x >> 5;
    int lane = threadIdx.x & 31;
    int g    = lane >> 3;
    int sub  = lane & 7;
    int node;
    if (uselist) {
        if (warp >= g_nlist) return;
        node = g_list[warp];
    } else {
        if (warp >= NN) return;
        node = warp;
    }
    int start = g_rowptr[node];
    int end   = g_rowptr[node + 1];
    ull a0 = 0, a1 = 0, a2 = 0, a3 = 0;
    int e0 = start;
    for (; e0 + 32 <= end; e0 += 32) {
        sedge[wid][lane] = g_edge[e0 + lane];
        __syncwarp();
        #pragma unroll
        for (int i0 = 0; i0 < 8; i0 += 4) {
            int2 eA = sedge[wid][4 * (i0 + 0) + g];
            int2 eB = sedge[wid][4 * (i0 + 1) + g];
            int2 eC = sedge[wid][4 * (i0 + 2) + g];
            int2 eD = sedge[wid][4 * (i0 + 3) + g];
            uint4 qA = B4[eA.x * 8 + sub];
            uint4 qB = B4[eB.x * 8 + sub];
            uint4 qC = B4[eC.x * 8 + sub];
            uint4 qD = B4[eD.x * 8 + sub];
            ull vA = pk2(__int_as_float(eA.y), __int_as_float(eA.y));
            ull vB = pk2(__int_as_float(eB.y), __int_as_float(eB.y));
            ull vC = pk2(__int_as_float(eC.y), __int_as_float(eC.y));
            ull vD = pk2(__int_as_float(eD.y), __int_as_float(eD.y));
            bfma(a0, qA.x, vA); bfma(a1, qA.y, vA); bfma(a2, qA.z, vA); bfma(a3, qA.w, vA);
            bfma(a0, qB.x, vB); bfma(a1, qB.y, vB); bfma(a2, qB.z, vB); bfma(a3, qB.w, vB);
            bfma(a0, qC.x, vC); bfma(a1, qC.y, vC); bfma(a2, qC.z, vC); bfma(a3, qC.w, vC);
            bfma(a0, qD.x, vD); bfma(a1, qD.y, vD); bfma(a2, qD.z, vD); bfma(a3, qD.w, vD);
        }
        __syncwarp();
    }
    int rem = end - e0;
    if (rem > 0) {
        sedge[wid][lane] = (lane < rem) ? g_edge[e0 + lane] : make_int2(0, 0);
        __syncwarp();
        int ngrp = (rem + 3) >> 2;
        for (int i = 0; i < ngrp; i++) {
            int2 ed = sedge[wid][4 * i + g];
            uint4 q = B4[ed.x * 8 + sub];
            ull vv = pk2(__int_as_float(ed.y), __int_as_float(ed.y));
            bfma(a0, q.x, vv); bfma(a1, q.y, vv); bfma(a2, q.z, vv); bfma(a3, q.w, vv);
        }
    }
    float2 f0 = upk(a0), f1 = upk(a1), f2 = upk(a2), f3 = upk(a3);
    #pragma unroll
    for (int off = 8; off <= 16; off <<= 1) {
        f0.x += __shfl_xor_sync(0xffffffffu, f0.x, off);
        f0.y += __shfl_xor_sync(0xffffffffu, f0.y, off);
        f1.x += __shfl_xor_sync(0xffffffffu, f1.x, off);
        f1.y += __shfl_xor_sync(0xffffffffu, f1.y, off);
        f2.x += __shfl_xor_sync(0xffffffffu, f2.x, off);
        f2.y += __shfl_xor_sync(0xffffffffu, f2.y, off);
        f3.x += __shfl_xor_sync(0xffffffffu, f3.x, off);
        f3.y += __shfl_xor_sync(0xffffffffu, f3.y, off);
    }
    if (lane < 8) {
        *(float4*)&g_Lmul[node * DD + lane * 8]     = make_float4(f0.x, f0.y, f1.x, f1.y);
        *(float4*)&g_Lmul[node * DD + lane * 8 + 4] = make_float4(f2.x, f2.y, f3.x, f3.y);
    }
}

// ---------------- 4: GEMM via mma.sync tf32 — 128 rows/block, 8 warps ---------
// R12 structure; last layer: rows mapped through g_list, writes alle only.
#define GP 68
#define OFF_AS 0
#define OFF_RS (128 * GP)
#define OFF_W1S (2 * 128 * GP)
#define OFF_W2S (2 * 128 * GP + 64 * GP)
#define OFF_BIAS (2 * 128 * GP + 2 * 64 * GP)
#define OFF_NID (OFF_BIAS + 64)
#define GEMM_SMEM_FLOATS (OFF_NID + 128)

__global__ void __launch_bounds__(256, 2) k_gemm(int cur, int l,
                                                 const float* __restrict__ W1,
                                                 const float* __restrict__ b1,
                                                 const float* __restrict__ W2,
                                                 const float* __restrict__ b2) {
    extern __shared__ float sm[];
    uint32_t* Au  = (uint32_t*)(sm + OFF_AS);    // [128][GP] tf32 bits
    uint32_t* Ru  = (uint32_t*)(sm + OFF_RS);    // [128][GP]
    uint32_t* W1u = (uint32_t*)(sm + OFF_W1S);   // [64][GP]  W'[n][k]
    uint32_t* W2u = (uint32_t*)(sm + OFF_W2S);   // [64][GP]
    float* biasS  = sm + OFF_BIAS;
    int*   nidS   = (int*)(sm + OFF_NID);        // per-row node id (-1 = skip)

    const float*  Ecur  = cur ? g_E1 : g_E0;
    float*        Enext = cur ? g_E0 : g_E1;
    unsigned int* Bnext = cur ? g_B0 : g_B1;

    int tid  = threadIdx.x;
    int wid  = tid >> 5;
    int lane = tid & 31;
    int g    = lane >> 2;        // 0..7
    int tg   = lane & 3;         // 0..3
    int rw   = wid * 16;         // warp's m16 tile base row
    int n0 = blockIdx.x * 128;
    int lw = l * 64 * 64;
    int lb = l * 64;
    int last = (l == NLAYERS - 1);

    if (tid < 64) biasS[tid] = b1[lb + tid] + b2[lb + tid];
    if (tid < 128) {
        int ni = n0 + tid;
        int n = -1;
        if (last) {
            if (ni < g_nlist) n = g_list[ni];
        } else {
            if (ni < NN) n = ni;
        }
        nidS[tid] = n;
    }
    __syncthreads();

    // ---- stage A = Lmul+E, R = Lmul*E (tf32-rounded); half-row per thread ----
    {
        int row  = tid >> 1;
        int half = (tid & 1) * 8;
        int n = nidS[row];
        const float4* LM4 = (const float4*)g_Lmul;
        const float4* EC4 = (const float4*)Ecur;
        #pragma unroll
        for (int cc = 0; cc < 8; cc++) {
            int c = half + cc;
            float4 lm = make_float4(0, 0, 0, 0), ev = make_float4(0, 0, 0, 0);
            if (n >= 0) {
                lm = LM4[n * 16 + c];
                ev = EC4[n * 16 + c];
            }
            uint4 av, rv;
            av.x = tf32r(lm.x + ev.x); av.y = tf32r(lm.y + ev.y);
            av.z = tf32r(lm.z + ev.z); av.w = tf32r(lm.w + ev.w);
            rv.x = tf32r(lm.x * ev.x); rv.y = tf32r(lm.y * ev.y);
            rv.z = tf32r(lm.z * ev.z); rv.w = tf32r(lm.w * ev.w);
            *(uint4*)&Au[row * GP + c * 4] = av;
            *(uint4*)&Ru[row * GP + c * 4] = rv;
        }
    }
    // ---- stage W' (transposed: W'[n][k] = W[k][n]), tf32-rounded ----
    {
        int j  = tid >> 2;
        int kq = (tid & 3) * 16;
        #pragma unroll
        for (int kk = 0; kk < 16; kk++) {
            int k = kq + kk;
            W1u[j * GP + k] = tf32r(W1[lw + k * 64 + j]);
            W2u[j * GP + k] = tf32r(W2[lw + k * 64 + j]);
        }
    }
    __syncthreads();

    // ---- accumulators: c[jt] covers rows {rw+g, rw+8+g}, cols {8jt+2tg, +1}
    float c[8][4];
    #pragma unroll
    for (int jt = 0; jt < 8; jt++) {
        float bv0 = biasS[8 * jt + 2 * tg];
        float bv1 = biasS[8 * jt + 2 * tg + 1];
        c[jt][0] = bv0; c[jt][1] = bv1;
        c[jt][2] = bv0; c[jt][3] = bv1;
    }

    #pragma unroll 2
    for (int kb = 0; kb < 64; kb += 8) {
        uint32_t af[4], rf[4];
        int rr = rw + g;
        af[0] = Au[rr * GP + kb + tg];
        af[1] = Au[(rr + 8) * GP + kb + tg];
        af[2] = Au[rr * GP + kb + tg + 4];
        af[3] = Au[(rr + 8) * GP + kb + tg + 4];
        rf[0] = Ru[rr * GP + kb + tg];
        rf[1] = Ru[(rr + 8) * GP + kb + tg];
        rf[2] = Ru[rr * GP + kb + tg + 4];
        rf[3] = Ru[(rr + 8) * GP + kb + tg + 4];
        #pragma unroll
        for (int jt = 0; jt < 8; jt++) {
            uint32_t w1f[2], w2f[2];
            int nn = 8 * jt + g;
            w1f[0] = W1u[nn * GP + kb + tg];
            w1f[1] = W1u[nn * GP + kb + tg + 4];
            w2f[0] = W2u[nn * GP + kb + tg];
            w2f[1] = W2u[nn * GP + kb + tg + 4];
            MMA_TF32(c[jt], af, w1f);
            MMA_TF32(c[jt], rf, w2f);
        }
    }

    // ---- leaky relu + per-row sq partials ----
    float sq[2] = {0, 0};
    #pragma unroll
    for (int jt = 0; jt < 8; jt++) {
        #pragma unroll
        for (int q = 0; q < 4; q++) {
            float v = c[jt][q];
            v = (v >= 0.0f) ? v : 0.2f * v;
            c[jt][q] = v;
            sq[q >> 1] = fmaf(v, v, sq[q >> 1]);
        }
    }
    sq[0] += __shfl_xor_sync(0xffffffffu, sq[0], 1);
    sq[0] += __shfl_xor_sync(0xffffffffu, sq[0], 2);
    sq[1] += __shfl_xor_sync(0xffffffffu, sq[1], 1);
    sq[1] += __shfl_xor_sync(0xffffffffu, sq[1], 2);

    __syncthreads();   // all fragment LDS done -> safe to reuse As/Rs
    float* OutS = sm + OFF_AS;        // [128][GP]
    float* sqS  = sm + OFF_RS;        // [128]
    {
        int rA = rw + g;
        #pragma unroll
        for (int jt = 0; jt < 8; jt++) {
            *(float2*)&OutS[rA * GP + 8 * jt + 2 * tg] =
                make_float2(c[jt][0], c[jt][1]);
            *(float2*)&OutS[(rA + 8) * GP + 8 * jt + 2 * tg] =
                make_float2(c[jt][2], c[jt][3]);
        }
        if (tg == 0) {
            sqS[rA]     = sq[0];
            sqS[rA + 8] = sq[1];
        }
    }
    __syncthreads();

    // ---- coalesced global writes ----
    {
        int tx = tid & 15;
        int ty = tid >> 4;           // 0..15
        int colblk = (l + 1) * 64;
        #pragma unroll 4
        for (int rr = 0; rr < 8; rr++) {
            int r = ty * 8 + rr;
            int n = nidS[r];
            if (n >= 0) {
                const float* o = &OutS[r * GP + tx * 4];
                float4 v = make_float4(o[0], o[1], o[2], o[3]);
                if (!last) {
                    *(float4*)&Enext[n * DD + tx * 4] = v;
                    uint2 bv;
                    bv.x = bf2pack(v.x, v.y);
                    bv.y = bf2pack(v.z, v.w);
                    *(uint2*)&Bnext[n * 32 + tx * 2] = bv;
                }
                if (last || g_need[n]) {
                    float inv = 1.0f / fmaxf(sqrtf(sqS[r]), 1e-12f);
                    *(float4*)&g_alle[n * 256 + colblk + tx * 4] =
                        make_float4(v.x * inv, v.y * inv, v.z * inv, v.w * inv);
                }
            }
        }
    }
}

// ---------------- 5: loss + fused finalize ----------------
__global__ void k_loss(const int* __restrict__ users,
                       const int* __restrict__ pos,
                       const int* __restrict__ neg,
                       float* __restrict__ out) {
    int warp = (blockIdx.x * blockDim.x + threadIdx.x) >> 5;
    int lane = threadIdx.x & 31;
    if (warp < NB) {
        int uu = users[warp];
        int pp = pos[warp];
        int nn = neg[warp];
        const float4* A4 = (const float4*)g_alle;
        float pd = 0, nd = 0, su = 0, sp = 0, sn = 0;
        #pragma unroll
        for (int t = 0; t < 2; t++) {
            float4 u = A4[uu * 64 + lane * 2 + t];
            float4 p = A4[pp * 64 + lane * 2 + t];
            float4 q = A4[nn * 64 + lane * 2 + t];
            pd += u.x * p.x + u.y * p.y + u.z * p.z + u.w * p.w;
            nd += u.x * q.x + u.y * q.y + u.z * q.z + u.w * q.w;
            su += u.x * u.x + u.y * u.y + u.z * u.z + u.w * u.w;
            sp += p.x * p.x + p.y * p.y + p.z * p.z + p.w * p.w;
            sn += q.x * q.x + q.y * q.y + q.z * q.z + q.w * q.w;
        }
        #pragma unroll
        for (int off = 16; off > 0; off >>= 1) {
            pd += __shfl_xor_sync(0xffffffffu, pd, off);
            nd += __shfl_xor_sync(0xffffffffu, nd, off);
            su += __shfl_xor_sync(0xffffffffu, su, off);
            sp += __shfl_xor_sync(0xffffffffu, sp, off);
            sn += __shfl_xor_sync(0xffffffffu, sn, off);
        }
        if (lane == 0) {
            float d = pd - nd;
            float ls = fminf(d, 0.0f) - log1pf(expf(-fabsf(d)));
            atomicAdd(&g_acc[0], ls);
            atomicAdd(&g_acc[1], su);
            atomicAdd(&g_acc[2], sp);
            atomicAdd(&g_acc[3], sn);
        }
    }
    __threadfence();
    __syncthreads();
    if (threadIdx.x == 0) {
        int r = atomicAdd(&g_done, 1);
        if (r == LOSS_NBLK - 1) {
            float a0 = atomicAdd(&g_acc[0], 0.0f);
            float a1 = atomicAdd(&g_acc[1], 0.0f);
            float a2 = atomicAdd(&g_acc[2], 0.0f);
            float a3 = atomicAdd(&g_acc[3], 0.0f);
            float bpr = -a0 / (float)NB;
            float l2norm = (a1 + a2 + sqrtf(a3)) * 0.5f;
            out[0] = bpr + L2_REG * l2norm / (float)NB;
            g_acc[0] = 0.0f; g_acc[1] = 0.0f; g_acc[2] = 0.0f; g_acc[3] = 0.0f;
            g_done = 0;
        }
    }
}

// ---------------- launch ----------------
extern "C" void kernel_launch(void* const* d_in, const int* in_sizes, int n_in,
                              void* d_out, int out_size) {
    const int*   users = (const int*)d_in[0];
    const int*   pos   = (const int*)d_in[1];
    const int*   neg   = (const int*)d_in[2];
    const int*   rows  = (const int*)d_in[3];
    const int*   cols  = (const int*)d_in[4];
    const float* vals  = (const float*)d_in[5];
    const float* ue    = (const float*)d_in[6];
    const float* ie    = (const float*)d_in[7];
    const float* W1    = (const float*)d_in[8];
    const float* b1    = (const float*)d_in[9];
    const float* W2    = (const float*)d_in[10];
    const float* b2    = (const float*)d_in[11];
    float* out = (float*)d_out;

    cudaFuncSetAttribute(k_gemm, cudaFuncAttributeMaxDynamicSharedMemorySize,
                         GEMM_SMEM_FLOATS * sizeof(float));

    // 0: mark sampled nodes + build list
    k_mark<<<(NB + 255) / 256, 256>>>(users, pos, neg);
    // 1: count + E init
    k_count_init<<<(NNZ + 255) / 256, 256>>>(rows, ue, ie);
    // 2: fused scan + scatter
    k_scan_scatter<<<SCAN_NBLK, SCAN_CHUNK>>>(rows, cols, vals);

    int cur = 0;
    for (int l = 0; l < NLAYERS; l++) {
        int last = (l == NLAYERS - 1);
        if (!last) {
            k_spmm<<<(NN + 7) / 8, 256>>>(cur, 0);
            k_gemm<<<(NN + 127) / 128, 256, GEMM_SMEM_FLOATS * sizeof(float)>>>(
                cur, l, W1, b1, W2, b2);
        } else {
            // sampled-node-only final layer (device-side count bound)
            k_spmm<<<(LIST_MAX + 7) / 8, 256>>>(cur, 1);
            k_gemm<<<(LIST_MAX + 127) / 128, 256, GEMM_SMEM_FLOATS * sizeof(float)>>>(
                cur, l, W1, b1, W2, b2);
        }
        cur ^= 1;
    }

    k_loss<<<LOSS_NBLK, 256>>>(users, pos, neg, out);
}